// round 3
// baseline (speedup 1.0000x reference)
#include <cuda_runtime.h>

#define B_ 4
#define N_ 4096
#define C_ 256
#define NSPLIT 32
#define M_ (B_*N_)          // 16384 rows total

typedef unsigned long long ull;

// ------------------------ device scratch (no allocs allowed) ------------------
__device__ float g_psum[2*B_*NSPLIT*C_];
__device__ float g_psq [2*B_*NSPLIT*C_];
__device__ float g_mean[2*B_*C_];
__device__ float g_rstd[2*B_*C_];
__device__ float g_Q[M_*C_];
__device__ float g_K[M_*C_];
__device__ float g_V[M_*C_];

// ------------------------ packed f32x2 helpers --------------------------------
__device__ __forceinline__ void fma2(ull& d, ull a, ull b){
    asm("fma.rn.f32x2 %0, %1, %2, %0;" : "+l"(d) : "l"(a), "l"(b));
}
__device__ __forceinline__ ull pack2(float x, float y){
    ull r; asm("mov.b64 %0, {%1, %2};" : "=l"(r) : "f"(x), "f"(y)); return r;
}
__device__ __forceinline__ float2 unpack2(ull v){
    float2 f; asm("mov.b64 {%0, %1}, %2;" : "=f"(f.x), "=f"(f.y) : "l"(v)); return f;
}

// ------------------------ instance-norm statistics ----------------------------
__global__ void k_stats_partial(const float* __restrict__ content,
                                const float* __restrict__ style){
    const float* x = blockIdx.z ? style : content;
    const int b = blockIdx.y, sp = blockIdx.x, c = threadIdx.x;
    const int rows = N_ / NSPLIT;                      // 128
    const float* base = x + (size_t)b*N_*C_ + (size_t)sp*rows*C_ + c;
    float s = 0.f, ss = 0.f;
    #pragma unroll 4
    for (int r = 0; r < rows; r++){
        float v = base[(size_t)r*C_];
        s += v; ss += v*v;
    }
    int idx = ((blockIdx.z*B_ + b)*NSPLIT + sp)*C_ + c;
    g_psum[idx] = s; g_psq[idx] = ss;
}

__global__ void k_stats_final(){
    const int b = blockIdx.x, t = blockIdx.y, c = threadIdx.x;
    float s = 0.f, ss = 0.f;
    #pragma unroll
    for (int sp = 0; sp < NSPLIT; sp++){
        int idx = ((t*B_ + b)*NSPLIT + sp)*C_ + c;
        s += g_psum[idx]; ss += g_psq[idx];
    }
    float mean = s * (1.f/N_);
    float var  = fmaxf(ss * (1.f/N_) - mean*mean, 0.f);
    g_mean[(t*B_ + b)*C_ + c] = mean;
    g_rstd[(t*B_ + b)*C_ + c] = rsqrtf(var + 1e-5f);
}

// ------------------------ fused norm + 1x1 conv GEMM --------------------------
// out = norm(A) @ W + bias   (normt: 0=content stats, 1=style stats, -1=no norm)
__global__ __launch_bounds__(256) void k_gemm(const float* __restrict__ A,
                                              const float* __restrict__ W,
                                              const float* __restrict__ bias,
                                              int normt, int which){
    __shared__ float As[16][68];
    __shared__ float Bs[16][68];
    float* out = (which == 0) ? g_Q : (which == 1) ? g_K : g_V;
    const int tid = threadIdx.x;
    const int tx = tid & 15, ty = tid >> 4;
    const int tm = blockIdx.x << 6, tn = blockIdx.y << 6;
    const int b = tm >> 12;
    const float* meanp = g_mean + (normt > 0 ? B_*C_ : 0) + b*C_;
    const float* rstdp = g_rstd + (normt > 0 ? B_*C_ : 0) + b*C_;
    const int lr = tid >> 2, lk = (tid & 3) << 2;
    const int wk = tid >> 4, wc = (tid & 15) << 2;
    float acc[4][4] = {};

    for (int k0 = 0; k0 < C_; k0 += 16){
        float4 av = *(const float4*)(A + (size_t)(tm + lr)*C_ + k0 + lk);
        if (normt >= 0){
            int cc = k0 + lk;
            av.x = (av.x - meanp[cc+0]) * rstdp[cc+0];
            av.y = (av.y - meanp[cc+1]) * rstdp[cc+1];
            av.z = (av.z - meanp[cc+2]) * rstdp[cc+2];
            av.w = (av.w - meanp[cc+3]) * rstdp[cc+3];
        }
        As[lk+0][lr] = av.x; As[lk+1][lr] = av.y;
        As[lk+2][lr] = av.z; As[lk+3][lr] = av.w;
        *(float4*)&Bs[wk][wc] = *(const float4*)(W + (size_t)(k0 + wk)*C_ + tn + wc);
        __syncthreads();
        #pragma unroll
        for (int kk = 0; kk < 16; kk++){
            float4 a  = *(const float4*)&As[kk][ty << 2];
            float4 bv = *(const float4*)&Bs[kk][tx << 2];
            acc[0][0] += a.x*bv.x; acc[0][1] += a.x*bv.y; acc[0][2] += a.x*bv.z; acc[0][3] += a.x*bv.w;
            acc[1][0] += a.y*bv.x; acc[1][1] += a.y*bv.y; acc[1][2] += a.y*bv.z; acc[1][3] += a.y*bv.w;
            acc[2][0] += a.z*bv.x; acc[2][1] += a.z*bv.y; acc[2][2] += a.z*bv.z; acc[2][3] += a.z*bv.w;
            acc[3][0] += a.w*bv.x; acc[3][1] += a.w*bv.y; acc[3][2] += a.w*bv.z; acc[3][3] += a.w*bv.w;
        }
        __syncthreads();
    }
    float4 bb = *(const float4*)(bias + tn + (tx << 2));
    #pragma unroll
    for (int r = 0; r < 4; r++){
        float4 o;
        o.x = acc[r][0] + bb.x; o.y = acc[r][1] + bb.y;
        o.z = acc[r][2] + bb.z; o.w = acc[r][3] + bb.w;
        *(float4*)(out + (size_t)(tm + (ty << 2) + r)*C_ + tn + (tx << 2)) = o;
    }
}

// ------------------------ l2norm rows of Q and K (in place) -------------------
__global__ void k_l2n(){
    const int w = threadIdx.x >> 5, l = threadIdx.x & 31;
    const size_t rid = (size_t)blockIdx.x * 8 + w;      // 0 .. 2*M_-1
    float* X = (rid < (size_t)M_) ? g_Q : g_K;
    float* p = X + (rid & (M_ - 1)) * C_;
    float4 a = *(float4*)(p + (l << 2));
    float4 c = *(float4*)(p + 128 + (l << 2));
    float ss = a.x*a.x + a.y*a.y + a.z*a.z + a.w*a.w
             + c.x*c.x + c.y*c.y + c.z*c.z + c.w*c.w;
    #pragma unroll
    for (int o = 16; o; o >>= 1) ss += __shfl_xor_sync(0xffffffffu, ss, o);
    float sc = rsqrtf(ss + 1e-12f);
    a.x *= sc; a.y *= sc; a.z *= sc; a.w *= sc;
    c.x *= sc; c.y *= sc; c.z *= sc; c.w *= sc;
    *(float4*)(p + (l << 2)) = a;
    *(float4*)(p + 128 + (l << 2)) = c;
}

// ------------------------ fused cosine attention + AdaIN ----------------------
// One CTA = 32 queries of one batch. Streams 32-key tiles.
// smem: Qs(32KB,swz) Ks(32KB,swz) Vs(32KB) V2(32KB) Es(32x33)
__global__ __launch_bounds__(256, 1) void k_attn(const float* __restrict__ content,
                                                 float* __restrict__ out){
    extern __shared__ float sm[];
    float* Qs = sm;
    float* Ks = sm + 8192;
    float* Vs = sm + 16384;
    float* V2 = sm + 24576;
    float* Es = sm + 32768;            // 32*33 floats

    const int tid = threadIdx.x;
    const int q = tid >> 3, g = tid & 7;
    const int q0 = blockIdx.x << 5;    // global query row
    const int b = q0 >> 12;
    const int kbase = b << 12;

    // load + swizzle Q tile (rows q0..q0+31)
    for (int it = tid; it < 2048; it += 256){
        int r = it >> 6, c4 = it & 63;
        float4 v = *(const float4*)(g_Q + (size_t)(q0 + r)*C_ + (c4 << 2));
        *(float4*)&Qs[((r << 6) + (c4 ^ (r & 7))) << 2] = v;
    }

    ull acc[16], ac2[16];
    #pragma unroll
    for (int i = 0; i < 16; i++){ acc[i] = 0ull; ac2[i] = 0ull; }
    float Z = 0.f;

    const ulonglong2* Qs4 = (const ulonglong2*)Qs;
    const ulonglong2* Ks4 = (const ulonglong2*)Ks;
    const ulonglong2* Vs4 = (const ulonglong2*)Vs;
    const ulonglong2* V24 = (const ulonglong2*)V2;
    const int qsw = q & 7;

    for (int kt = 0; kt < N_/32; kt++){
        __syncthreads();
        const size_t krow0 = (size_t)(kbase + (kt << 5));
        for (int it = tid; it < 2048; it += 256){
            int r = it >> 6, c4 = it & 63;
            size_t off = (krow0 + r)*C_ + (c4 << 2);
            *(float4*)&Ks[((r << 6) + (c4 ^ (r & 7))) << 2] = *(const float4*)(g_K + off);
            *(float4*)&Vs[it << 2] = *(const float4*)(g_V + off);
        }
        __syncthreads();

        // V^2 tile
        for (int it = tid; it < 2048; it += 256){
            float4 v = *(const float4*)&Vs[it << 2];
            v.x *= v.x; v.y *= v.y; v.z *= v.z; v.w *= v.w;
            *(float4*)&V2[it << 2] = v;
        }

        // logits: thread computes 4 logits (q, g+8jj), packed dot over k
        ull se[4], so[4];
        #pragma unroll
        for (int jj = 0; jj < 4; jj++){ se[jj] = 0ull; so[jj] = 0ull; }
        #pragma unroll 4
        for (int k4 = 0; k4 < 64; k4++){
            ulonglong2 qp = Qs4[(q << 6) + (k4 ^ qsw)];
            #pragma unroll
            for (int jj = 0; jj < 4; jj++){
                ulonglong2 kp = Ks4[((g + (jj << 3)) << 6) + (k4 ^ g)];
                fma2(se[jj], qp.x, kp.x);
                fma2(so[jj], qp.y, kp.y);
            }
        }
        #pragma unroll
        for (int jj = 0; jj < 4; jj++){
            float2 a = unpack2(se[jj]);
            float2 c = unpack2(so[jj]);
            Es[q*33 + g + (jj << 3)] = __expf(a.x + a.y + c.x + c.y);
        }
        __syncthreads();

        // accumulate Z, sum e*V, sum e*V^2 (thread owns channels 4*(g+8i)..+3)
        #pragma unroll 2
        for (int j = 0; j < 32; j++){
            float e = Es[q*33 + j];
            Z += e;
            ull ee = pack2(e, e);
            #pragma unroll
            for (int i = 0; i < 8; i++){
                int idx = (j << 6) + g + (i << 3);
                ulonglong2 v = Vs4[idx];
                ulonglong2 w = V24[idx];
                fma2(acc[2*i],   ee, v.x); fma2(acc[2*i+1], ee, v.y);
                fma2(ac2[2*i],   ee, w.x); fma2(ac2[2*i+1], ee, w.y);
            }
        }
    }

    // epilogue: M = acc/Z, S2 = ac2/Z - M^2, out = sqrt(relu(S2))*norm_content + M
    float invZ = 1.f / Z;
    const float* meanp = g_mean + b*C_;     // content stats (t=0)
    const float* rstdp = g_rstd + b*C_;
    size_t row = (size_t)(q0 + q)*C_;
    #pragma unroll
    for (int i = 0; i < 8; i++){
        int c = (g + (i << 3)) << 2;
        float2 m0 = unpack2(acc[2*i]),  m1 = unpack2(acc[2*i+1]);
        float2 s0 = unpack2(ac2[2*i]),  s1 = unpack2(ac2[2*i+1]);
        float4 cv = *(const float4*)(content + row + c);
        float4 o;
        float m, s2, s, nc;
        m = m0.x*invZ; s2 = s0.x*invZ - m*m; s = s2 > 0.f ? sqrtf(s2) : 0.f;
        nc = (cv.x - meanp[c+0])*rstdp[c+0]; o.x = s*nc + m;
        m = m0.y*invZ; s2 = s0.y*invZ - m*m; s = s2 > 0.f ? sqrtf(s2) : 0.f;
        nc = (cv.y - meanp[c+1])*rstdp[c+1]; o.y = s*nc + m;
        m = m1.x*invZ; s2 = s1.x*invZ - m*m; s = s2 > 0.f ? sqrtf(s2) : 0.f;
        nc = (cv.z - meanp[c+2])*rstdp[c+2]; o.z = s*nc + m;
        m = m1.y*invZ; s2 = s1.y*invZ - m*m; s = s2 > 0.f ? sqrtf(s2) : 0.f;
        nc = (cv.w - meanp[c+3])*rstdp[c+3]; o.w = s*nc + m;
        *(float4*)(out + row + c) = o;
    }
}

// ------------------------ launch ----------------------------------------------
extern "C" void kernel_launch(void* const* d_in, const int* in_sizes, int n_in,
                              void* d_out, int out_size){
    const float* content = (const float*)d_in[0];
    const float* style   = (const float*)d_in[1];
    const float* Wq = (const float*)d_in[2];
    const float* bq = (const float*)d_in[3];
    const float* Wk = (const float*)d_in[4];
    const float* bk = (const float*)d_in[5];
    const float* Wv = (const float*)d_in[6];
    const float* bv = (const float*)d_in[7];
    float* out = (float*)d_out;

    static const int SMEM_ATTN = (8192*4 + 32*33) * 4;   // 135296 bytes
    cudaFuncSetAttribute(k_attn, cudaFuncAttributeMaxDynamicSharedMemorySize, SMEM_ATTN);

    k_stats_partial<<<dim3(NSPLIT, B_, 2), 256>>>(content, style);
    k_stats_final<<<dim3(B_, 2), 256>>>();
    k_gemm<<<dim3(M_/64, C_/64), 256>>>(content, Wq, bq, 0, 0);
    k_gemm<<<dim3(M_/64, C_/64), 256>>>(style,   Wk, bk, 1, 1);
    k_gemm<<<dim3(M_/64, C_/64), 256>>>(style,   Wv, bv, -1, 2);
    k_l2n<<<2*M_/8, 256>>>();
    k_attn<<<M_/32, 256, SMEM_ATTN>>>(content, out);
}

// round 4
// speedup vs baseline: 1.9447x; 1.9447x over previous
#include <cuda_runtime.h>

#define B_ 4
#define N_ 4096
#define C_ 256
#define NSPLIT 32
#define M_ (B_*N_)          // 16384 rows total

#define QT 32               // query tile per CTA
#define KT 64               // key tile per iteration
#define KSPAN 2048          // keys per CTA (split-K = 2)
#define TPB 512

typedef unsigned long long ull;

// ------------------------ device scratch (no allocs allowed) ------------------
__device__ float g_psum[2*B_*NSPLIT*C_];
__device__ float g_psq [2*B_*NSPLIT*C_];
__device__ float g_mean[2*B_*C_];
__device__ float g_rstd[2*B_*C_];
__device__ float g_Q[M_*C_];
__device__ float g_K[M_*C_];
__device__ float g_V[M_*C_];
__device__ float g_pM[2*M_*C_];     // split partial sum e*V
__device__ float g_pS[2*M_*C_];     // split partial sum e*V^2
__device__ float g_pZ[2*M_];        // split partial sum e

// ------------------------ packed f32x2 helpers --------------------------------
__device__ __forceinline__ void fma2(ull& d, ull a, ull b){
    asm("fma.rn.f32x2 %0, %1, %2, %0;" : "+l"(d) : "l"(a), "l"(b));
}
__device__ __forceinline__ ull mul2(ull a, ull b){
    ull r; asm("mul.rn.f32x2 %0, %1, %2;" : "=l"(r) : "l"(a), "l"(b)); return r;
}
__device__ __forceinline__ ull pack2(float x, float y){
    ull r; asm("mov.b64 %0, {%1, %2};" : "=l"(r) : "f"(x), "f"(y)); return r;
}
__device__ __forceinline__ float2 unpack2(ull v){
    float2 f; asm("mov.b64 {%0, %1}, %2;" : "=f"(f.x), "=f"(f.y) : "l"(v)); return f;
}

// ------------------------ instance-norm statistics ----------------------------
__global__ void k_stats_partial(const float* __restrict__ content,
                                const float* __restrict__ style){
    const float* x = blockIdx.z ? style : content;
    const int b = blockIdx.y, sp = blockIdx.x, c = threadIdx.x;
    const int rows = N_ / NSPLIT;                      // 128
    const float* base = x + (size_t)b*N_*C_ + (size_t)sp*rows*C_ + c;
    float s = 0.f, ss = 0.f;
    #pragma unroll 4
    for (int r = 0; r < rows; r++){
        float v = base[(size_t)r*C_];
        s += v; ss += v*v;
    }
    int idx = ((blockIdx.z*B_ + b)*NSPLIT + sp)*C_ + c;
    g_psum[idx] = s; g_psq[idx] = ss;
}

__global__ void k_stats_final(){
    const int b = blockIdx.x, t = blockIdx.y, c = threadIdx.x;
    float s = 0.f, ss = 0.f;
    #pragma unroll
    for (int sp = 0; sp < NSPLIT; sp++){
        int idx = ((t*B_ + b)*NSPLIT + sp)*C_ + c;
        s += g_psum[idx]; ss += g_psq[idx];
    }
    float mean = s * (1.f/N_);
    float var  = fmaxf(ss * (1.f/N_) - mean*mean, 0.f);
    g_mean[(t*B_ + b)*C_ + c] = mean;
    g_rstd[(t*B_ + b)*C_ + c] = rsqrtf(var + 1e-5f);
}

// ------------------------ fused norm + 1x1 conv GEMM --------------------------
__global__ __launch_bounds__(256) void k_gemm(const float* __restrict__ A,
                                              const float* __restrict__ W,
                                              const float* __restrict__ bias,
                                              int normt, int which){
    __shared__ float As[16][68];
    __shared__ float Bs[16][68];
    float* out = (which == 0) ? g_Q : (which == 1) ? g_K : g_V;
    const int tid = threadIdx.x;
    const int tx = tid & 15, ty = tid >> 4;
    const int tm = blockIdx.x << 6, tn = blockIdx.y << 6;
    const int b = tm >> 12;
    const float* meanp = g_mean + (normt > 0 ? B_*C_ : 0) + b*C_;
    const float* rstdp = g_rstd + (normt > 0 ? B_*C_ : 0) + b*C_;
    const int lr = tid >> 2, lk = (tid & 3) << 2;
    const int wk = tid >> 4, wc = (tid & 15) << 2;
    float acc[4][4] = {};

    for (int k0 = 0; k0 < C_; k0 += 16){
        float4 av = *(const float4*)(A + (size_t)(tm + lr)*C_ + k0 + lk);
        if (normt >= 0){
            int cc = k0 + lk;
            av.x = (av.x - meanp[cc+0]) * rstdp[cc+0];
            av.y = (av.y - meanp[cc+1]) * rstdp[cc+1];
            av.z = (av.z - meanp[cc+2]) * rstdp[cc+2];
            av.w = (av.w - meanp[cc+3]) * rstdp[cc+3];
        }
        As[lk+0][lr] = av.x; As[lk+1][lr] = av.y;
        As[lk+2][lr] = av.z; As[lk+3][lr] = av.w;
        *(float4*)&Bs[wk][wc] = *(const float4*)(W + (size_t)(k0 + wk)*C_ + tn + wc);
        __syncthreads();
        #pragma unroll
        for (int kk = 0; kk < 16; kk++){
            float4 a  = *(const float4*)&As[kk][ty << 2];
            float4 bv = *(const float4*)&Bs[kk][tx << 2];
            acc[0][0] += a.x*bv.x; acc[0][1] += a.x*bv.y; acc[0][2] += a.x*bv.z; acc[0][3] += a.x*bv.w;
            acc[1][0] += a.y*bv.x; acc[1][1] += a.y*bv.y; acc[1][2] += a.y*bv.z; acc[1][3] += a.y*bv.w;
            acc[2][0] += a.z*bv.x; acc[2][1] += a.z*bv.y; acc[2][2] += a.z*bv.z; acc[2][3] += a.z*bv.w;
            acc[3][0] += a.w*bv.x; acc[3][1] += a.w*bv.y; acc[3][2] += a.w*bv.z; acc[3][3] += a.w*bv.w;
        }
        __syncthreads();
    }
    float4 bb = *(const float4*)(bias + tn + (tx << 2));
    #pragma unroll
    for (int r = 0; r < 4; r++){
        float4 o;
        o.x = acc[r][0] + bb.x; o.y = acc[r][1] + bb.y;
        o.z = acc[r][2] + bb.z; o.w = acc[r][3] + bb.w;
        *(float4*)(out + (size_t)(tm + (ty << 2) + r)*C_ + tn + (tx << 2)) = o;
    }
}

// ------------------------ l2norm rows of Q and K (in place) -------------------
__global__ void k_l2n(){
    const int w = threadIdx.x >> 5, l = threadIdx.x & 31;
    const size_t rid = (size_t)blockIdx.x * 8 + w;      // 0 .. 2*M_-1
    float* X = (rid < (size_t)M_) ? g_Q : g_K;
    float* p = X + (rid & (M_ - 1)) * C_;
    float4 a = *(float4*)(p + (l << 2));
    float4 c = *(float4*)(p + 128 + (l << 2));
    float ss = a.x*a.x + a.y*a.y + a.z*a.z + a.w*a.w
             + c.x*c.x + c.y*c.y + c.z*c.z + c.w*c.w;
    #pragma unroll
    for (int o = 16; o; o >>= 1) ss += __shfl_xor_sync(0xffffffffu, ss, o);
    float sc = rsqrtf(ss + 1e-12f);
    a.x *= sc; a.y *= sc; a.z *= sc; a.w *= sc;
    c.x *= sc; c.y *= sc; c.z *= sc; c.w *= sc;
    *(float4*)(p + (l << 2)) = a;
    *(float4*)(p + 128 + (l << 2)) = c;
}

// ------------------------ fused cosine attention (split-K partials) -----------
// grid (M_/QT, 2): CTA = 32 queries x 2048 keys. 512 threads.
// smem: Qs 32KB (swz), Ks 64KB (swz), Vs 64KB, Es 32x68, Zpart 32x4
__global__ __launch_bounds__(TPB, 1) void k_attn(){
    extern __shared__ float sm[];
    ulonglong2* Qs4 = (ulonglong2*)sm;                       // 32*64 entries
    ulonglong2* Ks4 = (ulonglong2*)(sm + 8192);              // 64*64 entries
    ulonglong2* Vs4 = (ulonglong2*)(sm + 8192 + 16384);      // 64*64 entries
    float* Es    = sm + 8192 + 16384 + 16384;                // [32][68]
    float* Zpart = Es + 32*68;                               // [32][4]

    const int tid = threadIdx.x;
    const int q0 = blockIdx.x * QT;
    const int sp = blockIdx.y;
    const int b  = q0 >> 12;
    const int kstart = (b << 12) + sp * KSPAN;

    // phase A indices: warp tiling 4x8 over (q-sub, k-row)
    const int warp = tid >> 5;
    const int wq = warp >> 2, wk = warp & 3;
    const int ql = (tid & 31) >> 3, kl = tid & 7;
    const int qr0 = wq*8 + ql, qr1 = qr0 + 4;
    const int kc0 = wk*16 + kl, kc1 = kc0 + 8;

    // phase B indices: 4 q-rows x 4 channels
    const int qg = tid >> 6;            // 0..7 -> rows qg*4..qg*4+3
    const int cg = tid & 63;            // channel quad

    // load Q tile (swizzled) + init Zpart
    {
        float4* Qsf = (float4*)Qs4;
        for (int it = tid; it < QT*64; it += TPB){
            int r = it >> 6, c4 = it & 63;
            Qsf[(r << 6) + (c4 ^ (r & 7))] =
                *(const float4*)(g_Q + (size_t)(q0 + r)*C_ + (c4 << 2));
        }
        if (tid < 128) Zpart[tid] = 0.f;
    }

    ull aM[4][2], aS[4][2];
    #pragma unroll
    for (int i = 0; i < 4; i++){ aM[i][0]=0ull; aM[i][1]=0ull; aS[i][0]=0ull; aS[i][1]=0ull; }

    float4* Ksf = (float4*)Ks4;
    float4* Vsf = (float4*)Vs4;

    for (int kt = 0; kt < KSPAN/KT; kt++){
        __syncthreads();
        // load K (swizzled) + V (plain)
        const size_t krow0 = (size_t)(kstart + kt*KT);
        for (int it = tid; it < KT*64; it += TPB){
            int r = it >> 6, c4 = it & 63;
            size_t off = (krow0 + r)*C_ + (c4 << 2);
            Ksf[(r << 6) + (c4 ^ (r & 7))] = *(const float4*)(g_K + off);
            Vsf[it] = *(const float4*)(g_V + off);
        }
        __syncthreads();

        // ---- phase A: 4 logits per thread (2q x 2k) ----
        ull a00=0ull, a01=0ull, a10=0ull, a11=0ull;
        const int qs0 = qr0 << 6, qs1 = qr1 << 6;
        const int ks0 = kc0 << 6, ks1 = kc1 << 6;
        const int qx0 = qr0 & 7, qx1 = qr1 & 7, kx0 = kc0 & 7, kx1 = kc1 & 7;
        #pragma unroll 8
        for (int k4 = 0; k4 < 64; k4++){
            ulonglong2 qa = Qs4[qs0 + (k4 ^ qx0)];
            ulonglong2 qb = Qs4[qs1 + (k4 ^ qx1)];
            ulonglong2 ka = Ks4[ks0 + (k4 ^ kx0)];
            ulonglong2 kb = Ks4[ks1 + (k4 ^ kx1)];
            fma2(a00, qa.x, ka.x); fma2(a00, qa.y, ka.y);
            fma2(a01, qa.x, kb.x); fma2(a01, qa.y, kb.y);
            fma2(a10, qb.x, ka.x); fma2(a10, qb.y, ka.y);
            fma2(a11, qb.x, kb.x); fma2(a11, qb.y, kb.y);
        }
        float2 f;
        f = unpack2(a00); float e00 = __expf(f.x + f.y);
        f = unpack2(a01); float e01 = __expf(f.x + f.y);
        f = unpack2(a10); float e10 = __expf(f.x + f.y);
        f = unpack2(a11); float e11 = __expf(f.x + f.y);
        Es[qr0*68 + kc0] = e00;  Es[qr0*68 + kc1] = e01;
        Es[qr1*68 + kc0] = e10;  Es[qr1*68 + kc1] = e11;
        // Z partial: butterfly over kl bits, unique writer per (q, wk)
        float s0 = e00 + e01, s1 = e10 + e11;
        #pragma unroll
        for (int o = 1; o < 8; o <<= 1){
            s0 += __shfl_xor_sync(0xffffffffu, s0, o);
            s1 += __shfl_xor_sync(0xffffffffu, s1, o);
        }
        if (kl == 0){
            Zpart[qr0*4 + wk] += s0;
            Zpart[qr1*4 + wk] += s1;
        }
        __syncthreads();

        // ---- phase B: accumulate e*V and e*V^2 (4q x 4ch per thread) ----
        const float* Eq = Es + (qg << 2)*68;
        #pragma unroll 2
        for (int j = 0; j < KT; j++){
            float e0 = Eq[j], e1 = Eq[68 + j], e2 = Eq[136 + j], e3 = Eq[204 + j];
            ull ee0 = pack2(e0, e0), ee1 = pack2(e1, e1);
            ull ee2 = pack2(e2, e2), ee3 = pack2(e3, e3);
            ulonglong2 v = Vs4[(j << 6) + cg];
            ull w0 = mul2(v.x, v.x), w1 = mul2(v.y, v.y);
            fma2(aM[0][0], ee0, v.x); fma2(aM[0][1], ee0, v.y);
            fma2(aM[1][0], ee1, v.x); fma2(aM[1][1], ee1, v.y);
            fma2(aM[2][0], ee2, v.x); fma2(aM[2][1], ee2, v.y);
            fma2(aM[3][0], ee3, v.x); fma2(aM[3][1], ee3, v.y);
            fma2(aS[0][0], ee0, w0);  fma2(aS[0][1], ee0, w1);
            fma2(aS[1][0], ee1, w0);  fma2(aS[1][1], ee1, w1);
            fma2(aS[2][0], ee2, w0);  fma2(aS[2][1], ee2, w1);
            fma2(aS[3][0], ee3, w0);  fma2(aS[3][1], ee3, w1);
        }
    }
    __syncthreads();

    // write partials
    const size_t pbase = ((size_t)sp*M_ + q0 + (qg << 2))*C_ + (cg << 2);
    #pragma unroll
    for (int i = 0; i < 4; i++){
        float2 mx = unpack2(aM[i][0]), my = unpack2(aM[i][1]);
        float2 sx = unpack2(aS[i][0]), sy = unpack2(aS[i][1]);
        float4 vm = {mx.x, mx.y, my.x, my.y};
        float4 vs = {sx.x, sx.y, sy.x, sy.y};
        *(float4*)(g_pM + pbase + (size_t)i*C_) = vm;
        *(float4*)(g_pS + pbase + (size_t)i*C_) = vs;
    }
    if (cg == 0){
        #pragma unroll
        for (int i = 0; i < 4; i++){
            int r = (qg << 2) + i;
            g_pZ[sp*M_ + q0 + r] = Zpart[r*4+0] + Zpart[r*4+1] + Zpart[r*4+2] + Zpart[r*4+3];
        }
    }
}

// ------------------------ reduce splits + AdaIN epilogue ----------------------
__global__ __launch_bounds__(256) void k_reduce(const float* __restrict__ content,
                                                float* __restrict__ out){
    int idx = blockIdx.x * 256 + threadIdx.x;     // over M_*64 channel-quads
    int row = idx >> 6, c = (idx & 63) << 2;
    int b = row >> 12;
    float Z = g_pZ[row] + g_pZ[M_ + row];
    float invZ = 1.f / Z;
    size_t o0 = (size_t)row*C_ + c;
    float4 m0 = *(const float4*)(g_pM + o0);
    float4 m1 = *(const float4*)(g_pM + (size_t)M_*C_ + o0);
    float4 s0 = *(const float4*)(g_pS + o0);
    float4 s1 = *(const float4*)(g_pS + (size_t)M_*C_ + o0);
    float4 cv = *(const float4*)(content + o0);
    const float* meanp = g_mean + b*C_;
    const float* rstdp = g_rstd + b*C_;
    float4 r;
    float m, s2, s, nc;
    m = (m0.x + m1.x)*invZ; s2 = (s0.x + s1.x)*invZ - m*m; s = s2 > 0.f ? sqrtf(s2) : 0.f;
    nc = (cv.x - meanp[c+0])*rstdp[c+0]; r.x = s*nc + m;
    m = (m0.y + m1.y)*invZ; s2 = (s0.y + s1.y)*invZ - m*m; s = s2 > 0.f ? sqrtf(s2) : 0.f;
    nc = (cv.y - meanp[c+1])*rstdp[c+1]; r.y = s*nc + m;
    m = (m0.z + m1.z)*invZ; s2 = (s0.z + s1.z)*invZ - m*m; s = s2 > 0.f ? sqrtf(s2) : 0.f;
    nc = (cv.z - meanp[c+2])*rstdp[c+2]; r.z = s*nc + m;
    m = (m0.w + m1.w)*invZ; s2 = (s0.w + s1.w)*invZ - m*m; s = s2 > 0.f ? sqrtf(s2) : 0.f;
    nc = (cv.w - meanp[c+3])*rstdp[c+3]; r.w = s*nc + m;
    *(float4*)(out + o0) = r;
}

// ------------------------ launch ----------------------------------------------
extern "C" void kernel_launch(void* const* d_in, const int* in_sizes, int n_in,
                              void* d_out, int out_size){
    const float* content = (const float*)d_in[0];
    const float* style   = (const float*)d_in[1];
    const float* Wq = (const float*)d_in[2];
    const float* bq = (const float*)d_in[3];
    const float* Wk = (const float*)d_in[4];
    const float* bk = (const float*)d_in[5];
    const float* Wv = (const float*)d_in[6];
    const float* bv = (const float*)d_in[7];
    float* out = (float*)d_out;

    const int SMEM_ATTN = (8192 + 16384 + 16384 + 32*68 + 32*4) * 4;  // 173056 B
    cudaFuncSetAttribute(k_attn, cudaFuncAttributeMaxDynamicSharedMemorySize, SMEM_ATTN);

    k_stats_partial<<<dim3(NSPLIT, B_, 2), 256>>>(content, style);
    k_stats_final<<<dim3(B_, 2), 256>>>();
    k_gemm<<<dim3(M_/64, C_/64), 256>>>(content, Wq, bq, 0, 0);
    k_gemm<<<dim3(M_/64, C_/64), 256>>>(style,   Wk, bk, 1, 1);
    k_gemm<<<dim3(M_/64, C_/64), 256>>>(style,   Wv, bv, -1, 2);
    k_l2n<<<2*M_/8, 256>>>();
    k_attn<<<dim3(M_/QT, 2), TPB, SMEM_ATTN>>>();
    k_reduce<<<M_*64/256, 256>>>(content, out);
}

// round 6
// speedup vs baseline: 11.5744x; 5.9518x over previous
#include <cuda_runtime.h>
#include <cuda_fp16.h>
#include <cstdint>

#define B_ 4
#define N_ 4096
#define C_ 256
#define NSPLIT 32
#define M_ (B_*N_)
#define L2E 1.4426950408889634f

// ---- attention smem layout (bytes) ----
#define QS_OFF   0          // 64x512  = 32768
#define KS_OFF   32768      // 2x 64x512 = 65536
#define VTS_OFF  98304      // 272x128 = 34816 (rows 256..271 = ones/zeros pad)
#define V2S_OFF  133120     // 256x128 = 32768
#define PS_OFF   165888     // 64x128  = 8192
#define ZS_OFF   174080     // 64x4    = 256
#define SMEM_ATT 174336

// ---------------- device scratch ----------------
__device__ float g_psum[2*B_*NSPLIT*C_];
__device__ float g_psq [2*B_*NSPLIT*C_];
__device__ float g_mean[2*B_*C_];
__device__ float g_rstd[2*B_*C_];
__device__ float g_Q[M_*C_];
__device__ float g_K[M_*C_];
__device__ float g_V[M_*C_];
__device__ __half g_Qh[M_*C_];              // l2norm'd, pre-scaled by log2(e)
__device__ __half g_Kh[M_*C_];              // l2norm'd
__device__ __half g_VTh[B_*C_*N_];          // [b][c][n]
__device__ __half g_VT2h[B_*C_*N_];         // [b][c][n] of v^2

// ---------------- PTX helpers ----------------
__device__ __forceinline__ uint32_t s2u(const void* p){
    uint32_t a;
    asm("{ .reg .u64 t; cvta.to.shared.u64 t, %1; cvt.u32.u64 %0, t; }" : "=r"(a) : "l"(p));
    return a;
}
__device__ __forceinline__ void ldm4(uint32_t a, uint32_t& r0, uint32_t& r1,
                                     uint32_t& r2, uint32_t& r3){
    asm volatile("ldmatrix.sync.aligned.m8n8.x4.shared.b16 {%0,%1,%2,%3}, [%4];"
        : "=r"(r0), "=r"(r1), "=r"(r2), "=r"(r3) : "r"(a));
}
__device__ __forceinline__ void mma16816(float* d, uint32_t a0, uint32_t a1,
                                         uint32_t a2, uint32_t a3,
                                         uint32_t b0, uint32_t b1){
    asm volatile("mma.sync.aligned.m16n8k16.row.col.f32.f16.f16.f32 "
        "{%0,%1,%2,%3},{%4,%5,%6,%7},{%8,%9},{%0,%1,%2,%3};"
        : "+f"(d[0]), "+f"(d[1]), "+f"(d[2]), "+f"(d[3])
        : "r"(a0), "r"(a1), "r"(a2), "r"(a3), "r"(b0), "r"(b1));
}
__device__ __forceinline__ void cpa16(uint32_t s, const void* g){
    asm volatile("cp.async.cg.shared.global [%0], [%1], 16;" :: "r"(s), "l"(g));
}
#define CPCOMMIT() asm volatile("cp.async.commit_group;")
#define CPWAIT(n)  asm volatile("cp.async.wait_group %0;" :: "n"(n))
// 2^t on a packed pair via one MUFU op; result is fp16x2 in mma fragment order
__device__ __forceinline__ uint32_t exp2_f16x2(float lo, float hi){
    uint32_t h, r;
    asm("cvt.rn.f16x2.f32 %0, %1, %2;" : "=r"(h) : "f"(hi), "f"(lo));
    asm("ex2.approx.f16x2 %0, %1;" : "=r"(r) : "r"(h));
    return r;
}

// ---------------- instance-norm statistics ----------------
__global__ void k_stats_partial(const float* __restrict__ content,
                                const float* __restrict__ style){
    const float* x = blockIdx.z ? style : content;
    const int b = blockIdx.y, sp = blockIdx.x, c = threadIdx.x;
    const int rows = N_ / NSPLIT;
    const float* base = x + (size_t)b*N_*C_ + (size_t)sp*rows*C_ + c;
    float s = 0.f, ss = 0.f;
    #pragma unroll 4
    for (int r = 0; r < rows; r++){
        float v = base[(size_t)r*C_];
        s += v; ss += v*v;
    }
    int idx = ((blockIdx.z*B_ + b)*NSPLIT + sp)*C_ + c;
    g_psum[idx] = s; g_psq[idx] = ss;
}

__global__ void k_stats_final(){
    const int b = blockIdx.x, t = blockIdx.y, c = threadIdx.x;
    float s = 0.f, ss = 0.f;
    #pragma unroll
    for (int sp = 0; sp < NSPLIT; sp++){
        int idx = ((t*B_ + b)*NSPLIT + sp)*C_ + c;
        s += g_psum[idx]; ss += g_psq[idx];
    }
    float mean = s * (1.f/N_);
    float var  = fmaxf(ss * (1.f/N_) - mean*mean, 0.f);
    g_mean[(t*B_ + b)*C_ + c] = mean;
    g_rstd[(t*B_ + b)*C_ + c] = rsqrtf(var + 1e-5f);
}

// ---------------- fused norm + 1x1 conv GEMM (fp32) ----------------
__global__ __launch_bounds__(256) void k_gemm(const float* __restrict__ A,
                                              const float* __restrict__ W,
                                              const float* __restrict__ bias,
                                              int normt, int which){
    __shared__ float As[16][68];
    __shared__ float Bs[16][68];
    float* out = (which == 0) ? g_Q : (which == 1) ? g_K : g_V;
    const int tid = threadIdx.x;
    const int tx = tid & 15, ty = tid >> 4;
    const int tm = blockIdx.x << 6, tn = blockIdx.y << 6;
    const int b = tm >> 12;
    const float* meanp = g_mean + (normt > 0 ? B_*C_ : 0) + b*C_;
    const float* rstdp = g_rstd + (normt > 0 ? B_*C_ : 0) + b*C_;
    const int lr = tid >> 2, lk = (tid & 3) << 2;
    const int wk = tid >> 4, wc = (tid & 15) << 2;
    float acc[4][4] = {};

    for (int k0 = 0; k0 < C_; k0 += 16){
        float4 av = *(const float4*)(A + (size_t)(tm + lr)*C_ + k0 + lk);
        if (normt >= 0){
            int cc = k0 + lk;
            av.x = (av.x - meanp[cc+0]) * rstdp[cc+0];
            av.y = (av.y - meanp[cc+1]) * rstdp[cc+1];
            av.z = (av.z - meanp[cc+2]) * rstdp[cc+2];
            av.w = (av.w - meanp[cc+3]) * rstdp[cc+3];
        }
        As[lk+0][lr] = av.x; As[lk+1][lr] = av.y;
        As[lk+2][lr] = av.z; As[lk+3][lr] = av.w;
        *(float4*)&Bs[wk][wc] = *(const float4*)(W + (size_t)(k0 + wk)*C_ + tn + wc);
        __syncthreads();
        #pragma unroll
        for (int kk = 0; kk < 16; kk++){
            float4 a  = *(const float4*)&As[kk][ty << 2];
            float4 bv = *(const float4*)&Bs[kk][tx << 2];
            acc[0][0] += a.x*bv.x; acc[0][1] += a.x*bv.y; acc[0][2] += a.x*bv.z; acc[0][3] += a.x*bv.w;
            acc[1][0] += a.y*bv.x; acc[1][1] += a.y*bv.y; acc[1][2] += a.y*bv.z; acc[1][3] += a.y*bv.w;
            acc[2][0] += a.z*bv.x; acc[2][1] += a.z*bv.y; acc[2][2] += a.z*bv.z; acc[2][3] += a.z*bv.w;
            acc[3][0] += a.w*bv.x; acc[3][1] += a.w*bv.y; acc[3][2] += a.w*bv.z; acc[3][3] += a.w*bv.w;
        }
        __syncthreads();
    }
    float4 bb = *(const float4*)(bias + tn + (tx << 2));
    #pragma unroll
    for (int r = 0; r < 4; r++){
        float4 o;
        o.x = acc[r][0] + bb.x; o.y = acc[r][1] + bb.y;
        o.z = acc[r][2] + bb.z; o.w = acc[r][3] + bb.w;
        *(float4*)(out + (size_t)(tm + (ty << 2) + r)*C_ + tn + (tx << 2)) = o;
    }
}

// ---------------- l2norm rows of Q,K -> fp16 (Q pre-scaled by log2 e) ----------
__global__ void k_l2n(){
    const int w = threadIdx.x >> 5, l = threadIdx.x & 31;
    const size_t rid = (size_t)blockIdx.x * 8 + w;      // 0 .. 2*M_-1
    const bool isQ = rid < (size_t)M_;
    const float* X = isQ ? g_Q : g_K;
    __half* O = isQ ? g_Qh : g_Kh;
    const size_t r = rid & (M_ - 1);
    const float* p = X + r*C_;
    float4 a = *(const float4*)(p + (l << 2));
    float4 c = *(const float4*)(p + 128 + (l << 2));
    float ss = a.x*a.x + a.y*a.y + a.z*a.z + a.w*a.w
             + c.x*c.x + c.y*c.y + c.z*c.z + c.w*c.w;
    #pragma unroll
    for (int o = 16; o; o >>= 1) ss += __shfl_xor_sync(0xffffffffu, ss, o);
    float sc = rsqrtf(ss + 1e-12f);
    if (isQ) sc *= L2E;
    __half2 h0 = __floats2half2_rn(a.x*sc, a.y*sc);
    __half2 h1 = __floats2half2_rn(a.z*sc, a.w*sc);
    __half2 h2 = __floats2half2_rn(c.x*sc, c.y*sc);
    __half2 h3 = __floats2half2_rn(c.z*sc, c.w*sc);
    uint2 u0; u0.x = *(uint32_t*)&h0; u0.y = *(uint32_t*)&h1;
    uint2 u1; u1.x = *(uint32_t*)&h2; u1.y = *(uint32_t*)&h3;
    *(uint2*)(O + r*C_ + (l << 2)) = u0;
    *(uint2*)(O + r*C_ + 128 + (l << 2)) = u1;
}

// ---------------- V transpose: g_V [b][n][c] -> VT/VT2 [b][c][n] fp16 ---------
__global__ void k_vt(){
    __shared__ float t[32][33];
    const int n0 = blockIdx.x << 5, c0 = blockIdx.y << 5, bb = blockIdx.z;
    for (int i = threadIdx.y; i < 32; i += 8)
        t[i][threadIdx.x] = g_V[((size_t)(bb*N_ + n0 + i))*C_ + c0 + threadIdx.x];
    __syncthreads();
    for (int i = threadIdx.y; i < 32; i += 8){
        float v = t[threadIdx.x][i];
        size_t o = ((size_t)(bb*C_ + c0 + i))*N_ + n0 + threadIdx.x;
        g_VTh[o]  = __float2half_rn(v);
        g_VT2h[o] = __float2half_rn(v*v);
    }
}

// ---------------- HMMA fused attention + AdaIN ----------------
// CTA = 64 queries x 256 channels x all 4096 keys. 256 threads (8 warps).
// Phase A warps: (wq 0..3) x (wk2 0..1): 16q x 32k logits each.
// Phase B warps: (wq 0..3) x (wc 0..1): 16q x 128ch accumulators each.
__global__ __launch_bounds__(256, 1) void k_attn_mma(const float* __restrict__ content,
                                                     float* __restrict__ out){
    extern __shared__ char sm[];
    const uint32_t sb = s2u(sm);
    const int tid = threadIdx.x, warp = tid >> 5, lane = tid & 31;
    const int q0 = blockIdx.x << 6;
    const int b  = q0 >> 12;
    const int wq = warp & 3, wk2 = warp >> 2, wc = wk2;
    const int mi = lane >> 3, r8 = lane & 7;
    const int l4 = lane >> 2, l2 = lane & 3;

    // ---- prologue: Q tile + K tile 0 via cp.async (group 0) ----
    for (int it = tid; it < 2048; it += 256){
        int r = it >> 5, c16 = it & 31;
        cpa16(sb + QS_OFF + r*512 + (((uint32_t)(c16 ^ (r & 7))) << 4),
              g_Qh + (((size_t)(q0 + r)) << 8) + (c16 << 3));
    }
    for (int it = tid; it < 2048; it += 256){
        int r = it >> 5, c16 = it & 31;
        cpa16(sb + KS_OFF + r*512 + (((uint32_t)(c16 ^ (r & 7))) << 4),
              g_Kh + (((size_t)((b << 12) + r)) << 8) + (c16 << 3));
    }
    CPCOMMIT();
    // ones/zero pad rows 256..271 of VT tile (for free Z via mma)
    if (tid < 128){
        int r = 256 + (tid >> 3), c16 = tid & 7;
        uint4 v = (r == 256) ? make_uint4(0x3C003C00u,0x3C003C00u,0x3C003C00u,0x3C003C00u)
                             : make_uint4(0u,0u,0u,0u);
        *(uint4*)(sm + VTS_OFF + r*128 + ((c16 ^ (r & 7)) << 4)) = v;
    }

    float accM[16][4], accV2[16][4], accZ[4];
    #pragma unroll
    for (int i = 0; i < 16; i++)
        #pragma unroll
        for (int j = 0; j < 4; j++){ accM[i][j] = 0.f; accV2[i][j] = 0.f; }
    #pragma unroll
    for (int j = 0; j < 4; j++) accZ[j] = 0.f;

    const __half* vt_base  = g_VTh  + (size_t)b*C_*N_;
    const __half* vt2_base = g_VT2h + (size_t)b*C_*N_;

    for (int kt = 0; kt < 64; kt++){
        __syncthreads();    // prev phase B done: V/V2/P reusable
        // V, V2 of current tile (groups +1, +2)
        for (int it = tid; it < 2048; it += 256){
            int r = it >> 3, c16 = it & 7;
            size_t gs = (((size_t)r) << 12) + (kt << 6) + (c16 << 3);
            cpa16(sb + VTS_OFF + r*128 + (((uint32_t)(c16 ^ (r & 7))) << 4), vt_base + gs);
        }
        CPCOMMIT();
        for (int it = tid; it < 2048; it += 256){
            int r = it >> 3, c16 = it & 7;
            size_t gs = (((size_t)r) << 12) + (kt << 6) + (c16 << 3);
            cpa16(sb + V2S_OFF + r*128 + (((uint32_t)(c16 ^ (r & 7))) << 4), vt2_base + gs);
        }
        CPCOMMIT();
        // prefetch K(kt+1) (group +3)
        {
            int ktn = (kt + 1) & 63;
            uint32_t kdst = sb + KS_OFF + ((kt + 1) & 1)*32768;
            for (int it = tid; it < 2048; it += 256){
                int r = it >> 5, c16 = it & 31;
                cpa16(kdst + r*512 + (((uint32_t)(c16 ^ (r & 7))) << 4),
                      g_Kh + (((size_t)((b << 12) + (ktn << 6) + r)) << 8) + (c16 << 3));
            }
        }
        CPCOMMIT();
        CPWAIT(3);          // K(kt) (and Q on kt==0) complete
        __syncthreads();

        // ---- phase A: S = Q @ K^T (16 c-steps), this warp: 16q x 32k ----
        const uint32_t kbase = sb + KS_OFF + (kt & 1)*32768;
        float d[4][4];
        #pragma unroll
        for (int i = 0; i < 4; i++){ d[i][0]=0.f; d[i][1]=0.f; d[i][2]=0.f; d[i][3]=0.f; }
        const uint32_t aA  = sb + QS_OFF + (uint32_t)((wq << 4) + r8 + ((mi & 1) << 3))*512;
        const uint32_t aB0 = kbase + (uint32_t)((wk2 << 5) + r8 + ((mi >> 1) << 3))*512;
        #pragma unroll
        for (int cs = 0; cs < 16; cs++){
            uint32_t a0,a1,a2,a3, b0,b1,b2,b3;
            ldm4(aA + (((uint32_t)((2*cs + (mi >> 1)) ^ r8)) << 4), a0,a1,a2,a3);
            uint32_t cB = ((uint32_t)((2*cs + (mi & 1)) ^ r8)) << 4;
            ldm4(aB0 + cB, b0,b1,b2,b3);
            mma16816(d[0], a0,a1,a2,a3, b0,b1);
            mma16816(d[1], a0,a1,a2,a3, b2,b3);
            ldm4(aB0 + 16*512 + cB, b0,b1,b2,b3);
            mma16816(d[2], a0,a1,a2,a3, b0,b1);
            mma16816(d[3], a0,a1,a2,a3, b2,b3);
        }
        // exp2 (logits pre-scaled by log2 e) -> P fp16 tile
        {
            const int qlo = (wq << 4) + l4;
            #pragma unroll
            for (int nt = 0; nt < 4; nt++){
                int c16p = (wk2 << 2) + nt;
                uint32_t sw = ((uint32_t)(c16p ^ l4)) << 4;    // qlo&7 == l4
                *(uint32_t*)(sm + PS_OFF + qlo*128 + sw + (l2 << 2))       = exp2_f16x2(d[nt][0], d[nt][1]);
                *(uint32_t*)(sm + PS_OFF + (qlo + 8)*128 + sw + (l2 << 2)) = exp2_f16x2(d[nt][2], d[nt][3]);
            }
        }
        CPWAIT(1);          // V, V2 complete (K(kt+1) may pend)
        __syncthreads();

        // ---- phase B: accM += P@V^T, accV2 += P@V2^T, accZ += P@ones ----
        const uint32_t aP = sb + PS_OFF + (uint32_t)((wq << 4) + r8 + ((mi & 1) << 3))*128;
        const uint32_t rowoff = (uint32_t)(r8 + ((mi >> 1) << 3))*128;
        #pragma unroll
        for (int s = 0; s < 4; s++){
            uint32_t p0,p1,p2,p3;
            ldm4(aP + (((uint32_t)((2*s + (mi >> 1)) ^ r8)) << 4), p0,p1,p2,p3);
            uint32_t cV = ((uint32_t)((2*s + (mi & 1)) ^ r8)) << 4;
            #pragma unroll
            for (int ctp = 0; ctp < 8; ctp++){
                uint32_t cb = (uint32_t)((wc << 7) + (ctp << 4));
                uint32_t v0,v1,v2,v3;
                ldm4(sb + VTS_OFF + cb*128 + rowoff + cV, v0,v1,v2,v3);
                mma16816(accM[2*ctp],   p0,p1,p2,p3, v0,v1);
                mma16816(accM[2*ctp+1], p0,p1,p2,p3, v2,v3);
                ldm4(sb + V2S_OFF + cb*128 + rowoff + cV, v0,v1,v2,v3);
                mma16816(accV2[2*ctp],   p0,p1,p2,p3, v0,v1);
                mma16816(accV2[2*ctp+1], p0,p1,p2,p3, v2,v3);
            }
            if (wc == 0){
                uint32_t z0,z1,z2,z3;
                ldm4(sb + VTS_OFF + 256*128 + rowoff + cV, z0,z1,z2,z3);
                mma16816(accZ, p0,p1,p2,p3, z0,z1);
            }
        }
    }
    CPWAIT(0);

    // ---- epilogue: Z broadcast, M/S2, AdaIN, store ----
    __syncthreads();
    float* Zs = (float*)(sm + ZS_OFF);
    if (wc == 0 && l2 == 0){
        Zs[(wq << 4) + l4]     = accZ[0];
        Zs[(wq << 4) + l4 + 8] = accZ[2];
    }
    __syncthreads();
    {
        const int qlo = (wq << 4) + l4;
        const float izlo = 1.f / Zs[qlo];
        const float izhi = 1.f / Zs[qlo + 8];
        const float* meanp = g_mean + b*C_;
        const float* rstdp = g_rstd + b*C_;
        const size_t glo = ((size_t)(q0 + qlo)) << 8;
        const size_t ghi = glo + (8u << 8);
        #pragma unroll
        for (int ct = 0; ct < 16; ct++){
            const int ch = (wc << 7) + (ct << 3) + (l2 << 1);
            const float mn0 = meanp[ch], mn1 = meanp[ch+1];
            const float rs0 = rstdp[ch], rs1 = rstdp[ch+1];
            {
                float2 cv = *(const float2*)(content + glo + ch);
                float m = accM[ct][0]*izlo;
                float s2 = accV2[ct][0]*izlo - m*m;
                float s = s2 > 0.f ? sqrtf(s2) : 0.f;
                float2 o;
                o.x = s*((cv.x - mn0)*rs0) + m;
                m = accM[ct][1]*izlo;
                s2 = accV2[ct][1]*izlo - m*m;
                s = s2 > 0.f ? sqrtf(s2) : 0.f;
                o.y = s*((cv.y - mn1)*rs1) + m;
                *(float2*)(out + glo + ch) = o;
            }
            {
                float2 cv = *(const float2*)(content + ghi + ch);
                float m = accM[ct][2]*izhi;
                float s2 = accV2[ct][2]*izhi - m*m;
                float s = s2 > 0.f ? sqrtf(s2) : 0.f;
                float2 o;
                o.x = s*((cv.x - mn0)*rs0) + m;
                m = accM[ct][3]*izhi;
                s2 = accV2[ct][3]*izhi - m*m;
                s = s2 > 0.f ? sqrtf(s2) : 0.f;
                o.y = s*((cv.y - mn1)*rs1) + m;
                *(float2*)(out + ghi + ch) = o;
            }
        }
    }
}

// ---------------- launch ----------------
extern "C" void kernel_launch(void* const* d_in, const int* in_sizes, int n_in,
                              void* d_out, int out_size){
    const float* content = (const float*)d_in[0];
    const float* style   = (const float*)d_in[1];
    const float* Wq = (const float*)d_in[2];
    const float* bq = (const float*)d_in[3];
    const float* Wk = (const float*)d_in[4];
    const float* bk = (const float*)d_in[5];
    const float* Wv = (const float*)d_in[6];
    const float* bv = (const float*)d_in[7];
    float* out = (float*)d_out;

    cudaFuncSetAttribute(k_attn_mma, cudaFuncAttributeMaxDynamicSharedMemorySize, SMEM_ATT);

    k_stats_partial<<<dim3(NSPLIT, B_, 2), 256>>>(content, style);
    k_stats_final<<<dim3(B_, 2), 256>>>();
    k_gemm<<<dim3(M_/64, C_/64), 256>>>(content, Wq, bq, 0, 0);
    k_gemm<<<dim3(M_/64, C_/64), 256>>>(style,   Wk, bk, 1, 1);
    k_gemm<<<dim3(M_/64, C_/64), 256>>>(style,   Wv, bv, -1, 2);
    k_l2n<<<2*M_/8, 256>>>();
    k_vt<<<dim3(N_/32, C_/32, B_), dim3(32, 8)>>>();
    k_attn_mma<<<M_/64, 256, SMEM_ATT>>>(content, out);
}

// round 7
// speedup vs baseline: 18.1250x; 1.5660x over previous
#include <cuda_runtime.h>
#include <cuda_fp16.h>
#include <cstdint>

#define B_ 4
#define N_ 4096
#define C_ 256
#define NSPLIT 32
#define M_ (B_*N_)
#define L2E 1.4426950408889634f

// ---- attention smem layout (bytes) ----
#define QS_OFF   0          // 64x512  = 32768
#define KS_OFF   32768      // 2x 64x512 = 65536
#define VTS_OFF  98304      // 256x128 = 32768
#define PS_OFF   131072     // 64x128  = 8192
#define SMEM_ATT 139264

#define ONESB 0x3C003C00u

// ---------------- device scratch ----------------
__device__ float g_psum[2*B_*NSPLIT*C_];
__device__ float g_psq [2*B_*NSPLIT*C_];
__device__ float g_mean[2*B_*C_];
__device__ float g_rstd[2*B_*C_];
__device__ __half g_Wth[3*C_*C_];           // W^T fp16: [which][n][k]
__device__ __half g_Qh[M_*C_];              // l2norm'd, pre-scaled by log2(e)
__device__ __half g_Kh[M_*C_];              // l2norm'd
__device__ __half g_VTh[B_*C_*N_];          // [b][c][n]

typedef unsigned long long ull;

// ---------------- PTX helpers ----------------
__device__ __forceinline__ uint32_t s2u(const void* p){
    uint32_t a;
    asm("{ .reg .u64 t; cvta.to.shared.u64 t, %1; cvt.u32.u64 %0, t; }" : "=r"(a) : "l"(p));
    return a;
}
__device__ __forceinline__ void ldm4(uint32_t a, uint32_t& r0, uint32_t& r1,
                                     uint32_t& r2, uint32_t& r3){
    asm volatile("ldmatrix.sync.aligned.m8n8.x4.shared.b16 {%0,%1,%2,%3}, [%4];"
        : "=r"(r0), "=r"(r1), "=r"(r2), "=r"(r3) : "r"(a));
}
__device__ __forceinline__ void mma16816(float* d, uint32_t a0, uint32_t a1,
                                         uint32_t a2, uint32_t a3,
                                         uint32_t b0, uint32_t b1){
    asm volatile("mma.sync.aligned.m16n8k16.row.col.f32.f16.f16.f32 "
        "{%0,%1,%2,%3},{%4,%5,%6,%7},{%8,%9},{%0,%1,%2,%3};"
        : "+f"(d[0]), "+f"(d[1]), "+f"(d[2]), "+f"(d[3])
        : "r"(a0), "r"(a1), "r"(a2), "r"(a3), "r"(b0), "r"(b1));
}
__device__ __forceinline__ void cpa16(uint32_t s, const void* g){
    asm volatile("cp.async.cg.shared.global [%0], [%1], 16;" :: "r"(s), "l"(g));
}
#define CPCOMMIT() asm volatile("cp.async.commit_group;")
#define CPWAIT(n)  asm volatile("cp.async.wait_group %0;" :: "n"(n))

__device__ __forceinline__ uint32_t exp2_f16x2(float lo, float hi){
    uint32_t h, r;
    asm("cvt.rn.f16x2.f32 %0, %1, %2;" : "=r"(h) : "f"(hi), "f"(lo));
    asm("ex2.approx.f16x2 %0, %1;" : "=r"(r) : "r"(h));
    return r;
}
__device__ __forceinline__ ull pack2(float x, float y){
    ull r; asm("mov.b64 %0, {%1, %2};" : "=l"(r) : "f"(x), "f"(y)); return r;
}
__device__ __forceinline__ float2 unpack2(ull v){
    float2 f; asm("mov.b64 {%0, %1}, %2;" : "=f"(f.x), "=f"(f.y) : "l"(v)); return f;
}
__device__ __forceinline__ ull fma2g(ull a, ull b, ull c){
    ull d; asm("fma.rn.f32x2 %0, %1, %2, %3;" : "=l"(d) : "l"(a), "l"(b), "l"(c)); return d;
}
__device__ __forceinline__ uint32_t sqr2(uint32_t v){
    uint32_t r; asm("mul.rn.f16x2 %0, %1, %1;" : "=r"(r) : "r"(v)); return r;
}
// degree-6 Taylor of 2^x (|x| <= 1.45, rel err < 6e-4), packed f32x2 -> f16x2
__device__ __forceinline__ uint32_t poly2_pair(float lo, float hi,
        ull C0, ull C1, ull C2, ull C3, ull C4, ull C5, ull C6){
    ull x = pack2(lo, hi);
    ull p = fma2g(C6, x, C5);
    p = fma2g(p, x, C4);
    p = fma2g(p, x, C3);
    p = fma2g(p, x, C2);
    p = fma2g(p, x, C1);
    p = fma2g(p, x, C0);
    float2 f = unpack2(p);
    uint32_t r;
    asm("cvt.rn.f16x2.f32 %0, %1, %2;" : "=r"(r) : "f"(f.y), "f"(f.x));
    return r;
}

// ---------------- instance-norm statistics ----------------
__global__ void k_stats_partial(const float* __restrict__ content,
                                const float* __restrict__ style){
    const float* x = blockIdx.z ? style : content;
    const int b = blockIdx.y, sp = blockIdx.x, c = threadIdx.x;
    const int rows = N_ / NSPLIT;
    const float* base = x + (size_t)b*N_*C_ + (size_t)sp*rows*C_ + c;
    float s = 0.f, ss = 0.f;
    #pragma unroll 4
    for (int r = 0; r < rows; r++){
        float v = base[(size_t)r*C_];
        s += v; ss += v*v;
    }
    int idx = ((blockIdx.z*B_ + b)*NSPLIT + sp)*C_ + c;
    g_psum[idx] = s; g_psq[idx] = ss;
}

__global__ void k_stats_final(){
    const int b = blockIdx.x, t = blockIdx.y, c = threadIdx.x;
    float s = 0.f, ss = 0.f;
    #pragma unroll
    for (int sp = 0; sp < NSPLIT; sp++){
        int idx = ((t*B_ + b)*NSPLIT + sp)*C_ + c;
        s += g_psum[idx]; ss += g_psq[idx];
    }
    float mean = s * (1.f/N_);
    float var  = fmaxf(ss * (1.f/N_) - mean*mean, 0.f);
    g_mean[(t*B_ + b)*C_ + c] = mean;
    g_rstd[(t*B_ + b)*C_ + c] = rsqrtf(var + 1e-5f);
}

// ---------------- W transpose + fp16 convert ----------------
__global__ void k_wcvt(const float* __restrict__ Wq, const float* __restrict__ Wk,
                       const float* __restrict__ Wv){
    __shared__ float t[32][33];
    const float* W = (blockIdx.z == 0) ? Wq : (blockIdx.z == 1) ? Wk : Wv;
    __half* O = g_Wth + (size_t)blockIdx.z*C_*C_;
    const int k0 = blockIdx.x << 5, n0 = blockIdx.y << 5;
    for (int i = threadIdx.y; i < 32; i += 8)
        t[i][threadIdx.x] = W[(size_t)(k0 + i)*C_ + n0 + threadIdx.x];
    __syncthreads();
    for (int i = threadIdx.y; i < 32; i += 8)
        O[(size_t)(n0 + i)*C_ + k0 + threadIdx.x] = __float2half_rn(t[threadIdx.x][i]);
}

// ---------------- fused norm + 1x1 conv (fp16 HMMA) + epilogues ---------------
// grid (M_/64, 3): which = 0 Q (l2norm*log2e), 1 K (l2norm), 2 V (transpose)
__global__ __launch_bounds__(256) void k_qkv(const float* __restrict__ content,
                                             const float* __restrict__ style,
                                             const float* __restrict__ bq,
                                             const float* __restrict__ bk,
                                             const float* __restrict__ bv){
    __shared__ __align__(16) char smem[40960];   // AS[0:8192) WS[8192:40960); T/ssm overlay
    const uint32_t sb = s2u(smem);
    const int tid = threadIdx.x, warp = tid >> 5, lane = tid & 31;
    const int wq2 = warp >> 2, wc4 = warp & 3;
    const int mi = lane >> 3, r8 = lane & 7, l4 = lane >> 2, l2 = lane & 3;
    const int which = blockIdx.y;
    const int tm = blockIdx.x << 6;
    const int b = tm >> 12;
    const float* A = (which == 0) ? content : style;
    const float* bias = (which == 0) ? bq : (which == 1) ? bk : bv;
    const __half* wsrc = g_Wth + (size_t)which*C_*C_;
    const float* meanp = g_mean + (which == 1 ? B_*C_ : 0) + b*C_;
    const float* rstdp = g_rstd + (which == 1 ? B_*C_ : 0) + b*C_;
    const bool donorm = which < 2;

    float acc[2][8][4];
    #pragma unroll
    for (int mt = 0; mt < 2; mt++)
        #pragma unroll
        for (int ct = 0; ct < 8; ct++){
            acc[mt][ct][0] = 0.f; acc[mt][ct][1] = 0.f;
            acc[mt][ct][2] = 0.f; acc[mt][ct][3] = 0.f;
        }

    for (int kc = 0; kc < 4; kc++){
        __syncthreads();
        // W chunk [256n][64k] via cp.async, swizzled
        for (int it = tid; it < 2048; it += 256){
            int n = it >> 3, c16 = it & 7;
            cpa16(sb + 8192 + n*128 + (((uint32_t)(c16 ^ (n & 7))) << 4),
                  wsrc + (size_t)n*C_ + (kc << 6) + (c16 << 3));
        }
        CPCOMMIT();
        // A chunk [64m][64k]: load fp32, norm, cvt fp16, swizzled store
        for (int it = tid; it < 1024; it += 256){
            int r = it >> 4, c4 = it & 15;
            int cc = (kc << 6) + (c4 << 2);
            float4 v = *(const float4*)(A + (size_t)(tm + r)*C_ + cc);
            if (donorm){
                float4 mn = *(const float4*)(meanp + cc);
                float4 rs = *(const float4*)(rstdp + cc);
                v.x = (v.x - mn.x)*rs.x; v.y = (v.y - mn.y)*rs.y;
                v.z = (v.z - mn.z)*rs.z; v.w = (v.w - mn.w)*rs.w;
            }
            __half2 h0 = __floats2half2_rn(v.x, v.y);
            __half2 h1 = __floats2half2_rn(v.z, v.w);
            uint2 u; u.x = *(uint32_t*)&h0; u.y = *(uint32_t*)&h1;
            int c16 = c4 >> 1, sub = c4 & 1;
            *(uint2*)(smem + (r << 7) + ((c16 ^ (r & 7)) << 4) + (sub << 3)) = u;
        }
        CPWAIT(0);
        __syncthreads();
        // mma: 4 k-steps
        #pragma unroll
        for (int cs = 0; cs < 4; cs++){
            uint32_t colA = ((uint32_t)((2*cs + (mi >> 1)) ^ r8)) << 4;
            uint32_t a00,a01,a02,a03, a10,a11,a12,a13;
            uint32_t aAb = sb + (uint32_t)((wq2 << 5) + r8 + ((mi & 1) << 3))*128;
            ldm4(aAb + colA, a00,a01,a02,a03);
            ldm4(aAb + 16*128 + colA, a10,a11,a12,a13);
            uint32_t colB = ((uint32_t)((2*cs + (mi & 1)) ^ r8)) << 4;
            #pragma unroll
            for (int ctp = 0; ctp < 4; ctp++){
                uint32_t w0,w1,w2,w3;
                ldm4(sb + 8192 + (uint32_t)((wc4 << 6) + (ctp << 4) + r8 + ((mi >> 1) << 3))*128 + colB,
                     w0,w1,w2,w3);
                mma16816(acc[0][2*ctp],   a00,a01,a02,a03, w0,w1);
                mma16816(acc[0][2*ctp+1], a00,a01,a02,a03, w2,w3);
                mma16816(acc[1][2*ctp],   a10,a11,a12,a13, w0,w1);
                mma16816(acc[1][2*ctp+1], a10,a11,a12,a13, w2,w3);
            }
        }
    }
    __syncthreads();

    // bias + (Q/K) row sum-of-squares
    float ssq[2][2] = {{0.f,0.f},{0.f,0.f}};
    #pragma unroll
    for (int mt = 0; mt < 2; mt++)
        #pragma unroll
        for (int ct = 0; ct < 8; ct++){
            int ch = (wc4 << 6) + (ct << 3) + (l2 << 1);
            float2 bb = *(const float2*)(bias + ch);
            acc[mt][ct][0] += bb.x; acc[mt][ct][1] += bb.y;
            acc[mt][ct][2] += bb.x; acc[mt][ct][3] += bb.y;
            if (which < 2){
                ssq[mt][0] += acc[mt][ct][0]*acc[mt][ct][0] + acc[mt][ct][1]*acc[mt][ct][1];
                ssq[mt][1] += acc[mt][ct][2]*acc[mt][ct][2] + acc[mt][ct][3]*acc[mt][ct][3];
            }
        }

    if (which < 2){
        #pragma unroll
        for (int mt = 0; mt < 2; mt++)
            #pragma unroll
            for (int h = 0; h < 2; h++){
                float v = ssq[mt][h];
                v += __shfl_xor_sync(0xffffffffu, v, 1);
                v += __shfl_xor_sync(0xffffffffu, v, 2);
                ssq[mt][h] = v;
            }
        float* ssm = (float*)smem;    // [4][64]
        if (l2 == 0){
            #pragma unroll
            for (int mt = 0; mt < 2; mt++){
                int rl = (wq2 << 5) + (mt << 4) + l4;
                ssm[wc4*64 + rl]     = ssq[mt][0];
                ssm[wc4*64 + rl + 8] = ssq[mt][1];
            }
        }
        __syncthreads();
        const float qsc = (which == 0) ? L2E : 1.f;
        __half* O = (which == 0) ? g_Qh : g_Kh;
        #pragma unroll
        for (int mt = 0; mt < 2; mt++){
            int rl = (wq2 << 5) + (mt << 4) + l4;
            float scl = rsqrtf(ssm[rl] + ssm[64+rl] + ssm[128+rl] + ssm[192+rl] + 1e-12f) * qsc;
            int rh = rl + 8;
            float sch = rsqrtf(ssm[rh] + ssm[64+rh] + ssm[128+rh] + ssm[192+rh] + 1e-12f) * qsc;
            #pragma unroll
            for (int ct = 0; ct < 8; ct++){
                int ch = (wc4 << 6) + (ct << 3) + (l2 << 1);
                __half2 h = __floats2half2_rn(acc[mt][ct][0]*scl, acc[mt][ct][1]*scl);
                *(uint32_t*)(O + (size_t)(tm + rl)*C_ + ch) = *(uint32_t*)&h;
                h = __floats2half2_rn(acc[mt][ct][2]*sch, acc[mt][ct][3]*sch);
                *(uint32_t*)(O + (size_t)(tm + rh)*C_ + ch) = *(uint32_t*)&h;
            }
        }
    } else {
        // V: stage [64m][264pad] fp16, then transposed write to g_VTh[b][c][n]
        __half* T = (__half*)smem;
        #pragma unroll
        for (int mt = 0; mt < 2; mt++){
            int rl = (wq2 << 5) + (mt << 4) + l4, rh = rl + 8;
            #pragma unroll
            for (int ct = 0; ct < 8; ct++){
                int ch = (wc4 << 6) + (ct << 3) + (l2 << 1);
                __half2 h = __floats2half2_rn(acc[mt][ct][0], acc[mt][ct][1]);
                *(uint32_t*)&T[rl*264 + ch] = *(uint32_t*)&h;
                h = __floats2half2_rn(acc[mt][ct][2], acc[mt][ct][3]);
                *(uint32_t*)&T[rh*264 + ch] = *(uint32_t*)&h;
            }
        }
        __syncthreads();
        const int c = tid;
        const int n0 = tm & (N_ - 1);
        __half* Ov = g_VTh + ((size_t)(b*C_ + c))*N_ + n0;
        #pragma unroll
        for (int j = 0; j < 8; j++){
            __half hh[8];
            #pragma unroll
            for (int i = 0; i < 8; i++) hh[i] = T[(j*8 + i)*264 + c];
            *(uint4*)(Ov + j*8) = *(uint4*)hh;
        }
    }
}

// ---------------- HMMA fused attention + AdaIN ----------------
// CTA = 64 queries x 256 channels x all 4096 keys. 256 threads (8 warps).
__global__ __launch_bounds__(256, 1) void k_attn_mma(const float* __restrict__ content,
                                                     float* __restrict__ out){
    extern __shared__ char sm[];
    const uint32_t sb = s2u(sm);
    const int tid = threadIdx.x, warp = tid >> 5, lane = tid & 31;
    const int q0 = blockIdx.x << 6;
    const int b  = q0 >> 12;
    const int wq = warp & 3, wk2 = warp >> 2;        // phase A tiling
    const int wq2 = warp >> 2, wc4 = warp & 3;       // phase B tiling
    const int mi = lane >> 3, r8 = lane & 7;
    const int l4 = lane >> 2, l2 = lane & 3;

    const ull C0p = pack2(1.0f, 1.0f);
    const ull C1p = pack2(0.69314718f, 0.69314718f);
    const ull C2p = pack2(0.24022651f, 0.24022651f);
    const ull C3p = pack2(0.055504109f, 0.055504109f);
    const ull C4p = pack2(0.0096181291f, 0.0096181291f);
    const ull C5p = pack2(0.0013333558f, 0.0013333558f);
    const ull C6p = pack2(1.5403530e-4f, 1.5403530e-4f);

    // prologue: Q + K(0), one cp.async group
    for (int it = tid; it < 2048; it += 256){
        int r = it >> 5, c16 = it & 31;
        cpa16(sb + QS_OFF + r*512 + (((uint32_t)(c16 ^ (r & 7))) << 4),
              g_Qh + (((size_t)(q0 + r)) << 8) + (c16 << 3));
    }
    for (int it = tid; it < 2048; it += 256){
        int r = it >> 5, c16 = it & 31;
        cpa16(sb + KS_OFF + r*512 + (((uint32_t)(c16 ^ (r & 7))) << 4),
              g_Kh + (((size_t)((b << 12) + r)) << 8) + (c16 << 3));
    }
    CPCOMMIT();

    float accM[2][8][4], accV2[2][8][4], accZ[2][4];
    #pragma unroll
    for (int mt = 0; mt < 2; mt++){
        #pragma unroll
        for (int ct = 0; ct < 8; ct++)
            #pragma unroll
            for (int j = 0; j < 4; j++){ accM[mt][ct][j] = 0.f; accV2[mt][ct][j] = 0.f; }
        #pragma unroll
        for (int j = 0; j < 4; j++) accZ[mt][j] = 0.f;
    }

    const __half* vt_base = g_VTh + (size_t)b*C_*N_;

    for (int kt = 0; kt < 64; kt++){
        __syncthreads();     // previous tile's P/VT consumed
        // VT(kt): [256c][64k]
        for (int it = tid; it < 2048; it += 256){
            int r = it >> 3, c16 = it & 7;
            cpa16(sb + VTS_OFF + r*128 + (((uint32_t)(c16 ^ (r & 7))) << 4),
                  vt_base + (((size_t)r) << 12) + (kt << 6) + (c16 << 3));
        }
        CPCOMMIT();
        // K(kt+1) prefetch
        {
            int ktn = (kt + 1) & 63;
            uint32_t kdst = sb + KS_OFF + ((kt + 1) & 1)*32768;
            for (int it = tid; it < 2048; it += 256){
                int r = it >> 5, c16 = it & 31;
                cpa16(kdst + r*512 + (((uint32_t)(c16 ^ (r & 7))) << 4),
                      g_Kh + (((size_t)((b << 12) + (ktn << 6) + r)) << 8) + (c16 << 3));
            }
        }
        CPCOMMIT();
        CPWAIT(2);           // K(kt) ready (and Q on kt==0)
        __syncthreads();

        // ---- phase A: S = Q @ K^T, warp: 16q x 32k ----
        const uint32_t kbase = sb + KS_OFF + (kt & 1)*32768;
        float d[4][4];
        #pragma unroll
        for (int i = 0; i < 4; i++){ d[i][0]=0.f; d[i][1]=0.f; d[i][2]=0.f; d[i][3]=0.f; }
        const uint32_t aA  = sb + QS_OFF + (uint32_t)((wq << 4) + r8 + ((mi & 1) << 3))*512;
        const uint32_t aB0 = kbase + (uint32_t)((wk2 << 5) + r8 + ((mi >> 1) << 3))*512;
        #pragma unroll
        for (int cs = 0; cs < 16; cs++){
            uint32_t a0,a1,a2,a3, b0,b1,b2,b3;
            ldm4(aA + (((uint32_t)((2*cs + (mi >> 1)) ^ r8)) << 4), a0,a1,a2,a3);
            uint32_t cB = ((uint32_t)((2*cs + (mi & 1)) ^ r8)) << 4;
            ldm4(aB0 + cB, b0,b1,b2,b3);
            mma16816(d[0], a0,a1,a2,a3, b0,b1);
            mma16816(d[1], a0,a1,a2,a3, b2,b3);
            ldm4(aB0 + 16*512 + cB, b0,b1,b2,b3);
            mma16816(d[2], a0,a1,a2,a3, b0,b1);
            mma16816(d[3], a0,a1,a2,a3, b2,b3);
        }
        // hybrid exp2: nt==0 via f32x2 poly (fma pipe), nt 1..3 via MUFU
        {
            const int qlo = (wq << 4) + l4;
            #pragma unroll
            for (int nt = 0; nt < 4; nt++){
                uint32_t plo, phi;
                if (nt == 0){
                    plo = poly2_pair(d[nt][0], d[nt][1], C0p,C1p,C2p,C3p,C4p,C5p,C6p);
                    phi = poly2_pair(d[nt][2], d[nt][3], C0p,C1p,C2p,C3p,C4p,C5p,C6p);
                } else {
                    plo = exp2_f16x2(d[nt][0], d[nt][1]);
                    phi = exp2_f16x2(d[nt][2], d[nt][3]);
                }
                int c16p = (wk2 << 2) + nt;
                uint32_t sw = ((uint32_t)(c16p ^ l4)) << 4;
                *(uint32_t*)(sm + PS_OFF + qlo*128 + sw + (l2 << 2))       = plo;
                *(uint32_t*)(sm + PS_OFF + (qlo + 8)*128 + sw + (l2 << 2)) = phi;
            }
        }
        CPWAIT(1);           // VT(kt) ready
        __syncthreads();

        // ---- phase B: warp = 32q x 64ch; V^2 in regs; Z via ones-frag ----
        const uint32_t aPb = sb + PS_OFF + (uint32_t)((wq2 << 5) + r8 + ((mi & 1) << 3))*128;
        const uint32_t aVb = sb + VTS_OFF + (uint32_t)((wc4 << 6) + r8 + ((mi >> 1) << 3))*128;
        #pragma unroll
        for (int s = 0; s < 4; s++){
            uint32_t colA = ((uint32_t)((2*s + (mi >> 1)) ^ r8)) << 4;
            uint32_t p00,p01,p02,p03, p10,p11,p12,p13;
            ldm4(aPb + colA, p00,p01,p02,p03);
            ldm4(aPb + 16*128 + colA, p10,p11,p12,p13);
            uint32_t colB = ((uint32_t)((2*s + (mi & 1)) ^ r8)) << 4;
            #pragma unroll
            for (int ctp = 0; ctp < 4; ctp++){
                uint32_t v0,v1,v2,v3;
                ldm4(aVb + (uint32_t)(ctp << 4)*128 + colB, v0,v1,v2,v3);
                mma16816(accM[0][2*ctp],   p00,p01,p02,p03, v0,v1);
                mma16816(accM[0][2*ctp+1], p00,p01,p02,p03, v2,v3);
                mma16816(accM[1][2*ctp],   p10,p11,p12,p13, v0,v1);
                mma16816(accM[1][2*ctp+1], p10,p11,p12,p13, v2,v3);
                uint32_t w0 = sqr2(v0), w1 = sqr2(v1), w2 = sqr2(v2), w3 = sqr2(v3);
                mma16816(accV2[0][2*ctp],   p00,p01,p02,p03, w0,w1);
                mma16816(accV2[0][2*ctp+1], p00,p01,p02,p03, w2,w3);
                mma16816(accV2[1][2*ctp],   p10,p11,p12,p13, w0,w1);
                mma16816(accV2[1][2*ctp+1], p10,p11,p12,p13, w2,w3);
            }
            mma16816(accZ[0], p00,p01,p02,p03, ONESB, ONESB);
            mma16816(accZ[1], p10,p11,p12,p13, ONESB, ONESB);
        }
    }
    CPWAIT(0);

    // ---- epilogue: per-lane Z, M/S2, AdaIN, store ----
    const float* meanp = g_mean + b*C_;
    const float* rstdp = g_rstd + b*C_;
    #pragma unroll
    for (int mt = 0; mt < 2; mt++){
        const float izlo = 1.f / accZ[mt][0];
        const float izhi = 1.f / accZ[mt][2];
        const int rl = q0 + (wq2 << 5) + (mt << 4) + l4;
        const size_t glo = ((size_t)rl) << 8;
        const size_t ghi = ((size_t)(rl + 8)) << 8;
        #pragma unroll
        for (int ct = 0; ct < 8; ct++){
            const int ch = (wc4 << 6) + (ct << 3) + (l2 << 1);
            const float mn0 = meanp[ch], mn1 = meanp[ch+1];
            const float rs0 = rstdp[ch], rs1 = rstdp[ch+1];
            {
                float2 cv = *(const float2*)(content + glo + ch);
                float m = accM[mt][ct][0]*izlo;
                float s2 = accV2[mt][ct][0]*izlo - m*m;
                float s = s2 > 0.f ? sqrtf(s2) : 0.f;
                float2 o;
                o.x = s*((cv.x - mn0)*rs0) + m;
                m = accM[mt][ct][1]*izlo;
                s2 = accV2[mt][ct][1]*izlo - m*m;
                s = s2 > 0.f ? sqrtf(s2) : 0.f;
                o.y = s*((cv.y - mn1)*rs1) + m;
                *(float2*)(out + glo + ch) = o;
            }
            {
                float2 cv = *(const float2*)(content + ghi + ch);
                float m = accM[mt][ct][2]*izhi;
                float s2 = accV2[mt][ct][2]*izhi - m*m;
                float s = s2 > 0.f ? sqrtf(s2) : 0.f;
                float2 o;
                o.x = s*((cv.x - mn0)*rs0) + m;
                m = accM[mt][ct][3]*izhi;
                s2 = accV2[mt][ct][3]*izhi - m*m;
                s = s2 > 0.f ? sqrtf(s2) : 0.f;
                o.y = s*((cv.y - mn1)*rs1) + m;
                *(float2*)(out + ghi + ch) = o;
            }
        }
    }
}

// ---------------- launch ----------------
extern "C" void kernel_launch(void* const* d_in, const int* in_sizes, int n_in,
                              void* d_out, int out_size){
    const float* content = (const float*)d_in[0];
    const float* style   = (const float*)d_in[1];
    const float* Wq = (const float*)d_in[2];
    const float* bq = (const float*)d_in[3];
    const float* Wk = (const float*)d_in[4];
    const float* bk = (const float*)d_in[5];
    const float* Wv = (const float*)d_in[6];
    const float* bv = (const float*)d_in[7];
    float* out = (float*)d_out;

    cudaFuncSetAttribute(k_attn_mma, cudaFuncAttributeMaxDynamicSharedMemorySize, SMEM_ATT);

    k_stats_partial<<<dim3(NSPLIT, B_, 2), 256>>>(content, style);
    k_stats_final<<<dim3(B_, 2), 256>>>();
    k_wcvt<<<dim3(8, 8, 3), dim3(32, 8)>>>(Wq, Wk, Wv);
    k_qkv<<<dim3(M_/64, 3), 256>>>(content, style, bq, bk, bv);
    k_attn_mma<<<M_/64, 256, SMEM_ATT>>>(content, out);
}

// round 8
// speedup vs baseline: 19.1032x; 1.0540x over previous
#include <cuda_runtime.h>
#include <cuda_fp16.h>
#include <cstdint>

#define B_ 4
#define N_ 4096
#define C_ 256
#define NSPLIT 32
#define M_ (B_*N_)
#define L2E 1.4426950408889634f

// ---- attention smem layout (bytes) ----
#define QS_OFF   0          // 64x512  = 32768
#define KS_OFF   32768      // 2x 64x512 = 65536
#define VTS_OFF  98304      // 256x128 = 32768
#define PS_OFF   131072     // 64x128  = 8192 (reused for Z exchange)
#define SMEM_ATT 139264

// ---------------- device scratch ----------------
__device__ float g_psum[2*B_*NSPLIT*C_];
__device__ float g_psq [2*B_*NSPLIT*C_];
__device__ float g_mean[2*B_*C_];
__device__ float g_rstd[2*B_*C_];
__device__ __half g_Wth[3*C_*C_];           // W^T fp16: [which][n][k]
__device__ __half g_Qh[M_*C_];              // l2norm'd, pre-scaled by log2(e)
__device__ __half g_Kh[M_*C_];              // l2norm'd
__device__ __half g_VTh[B_*C_*N_];          // [b][c][n]

typedef unsigned long long ull;

// ---------------- PTX helpers ----------------
__device__ __forceinline__ uint32_t s2u(const void* p){
    uint32_t a;
    asm("{ .reg .u64 t; cvta.to.shared.u64 t, %1; cvt.u32.u64 %0, t; }" : "=r"(a) : "l"(p));
    return a;
}
__device__ __forceinline__ void ldm4(uint32_t a, uint32_t& r0, uint32_t& r1,
                                     uint32_t& r2, uint32_t& r3){
    asm volatile("ldmatrix.sync.aligned.m8n8.x4.shared.b16 {%0,%1,%2,%3}, [%4];"
        : "=r"(r0), "=r"(r1), "=r"(r2), "=r"(r3) : "r"(a));
}
__device__ __forceinline__ void mma16816(float* d, uint32_t a0, uint32_t a1,
                                         uint32_t a2, uint32_t a3,
                                         uint32_t b0, uint32_t b1){
    asm volatile("mma.sync.aligned.m16n8k16.row.col.f32.f16.f16.f32 "
        "{%0,%1,%2,%3},{%4,%5,%6,%7},{%8,%9},{%0,%1,%2,%3};"
        : "+f"(d[0]), "+f"(d[1]), "+f"(d[2]), "+f"(d[3])
        : "r"(a0), "r"(a1), "r"(a2), "r"(a3), "r"(b0), "r"(b1));
}
__device__ __forceinline__ void cpa16(uint32_t s, const void* g){
    asm volatile("cp.async.cg.shared.global [%0], [%1], 16;" :: "r"(s), "l"(g));
}
#define CPCOMMIT() asm volatile("cp.async.commit_group;")
#define CPWAIT(n)  asm volatile("cp.async.wait_group %0;" :: "n"(n))

__device__ __forceinline__ uint32_t exp2_f16x2(float lo, float hi){
    uint32_t h, r;
    asm("cvt.rn.f16x2.f32 %0, %1, %2;" : "=r"(h) : "f"(hi), "f"(lo));
    asm("ex2.approx.f16x2 %0, %1;" : "=r"(r) : "r"(h));
    return r;
}
__device__ __forceinline__ uint32_t sqr2(uint32_t v){
    uint32_t r; asm("mul.rn.f16x2 %0, %1, %1;" : "=r"(r) : "r"(v)); return r;
}
__device__ __forceinline__ float hsum2(uint32_t h2){
    __half2 h = *(__half2*)&h2;
    float2 f = __half22float2(h);
    return f.x + f.y;
}

// ---------------- instance-norm statistics ----------------
__global__ void k_stats_partial(const float* __restrict__ content,
                                const float* __restrict__ style){
    const float* x = blockIdx.z ? style : content;
    const int b = blockIdx.y, sp = blockIdx.x, c = threadIdx.x;
    const int rows = N_ / NSPLIT;
    const float* base = x + (size_t)b*N_*C_ + (size_t)sp*rows*C_ + c;
    float s = 0.f, ss = 0.f;
    #pragma unroll 4
    for (int r = 0; r < rows; r++){
        float v = base[(size_t)r*C_];
        s += v; ss += v*v;
    }
    int idx = ((blockIdx.z*B_ + b)*NSPLIT + sp)*C_ + c;
    g_psum[idx] = s; g_psq[idx] = ss;
}

__global__ void k_stats_final(){
    const int b = blockIdx.x, t = blockIdx.y, c = threadIdx.x;
    float s = 0.f, ss = 0.f;
    #pragma unroll
    for (int sp = 0; sp < NSPLIT; sp++){
        int idx = ((t*B_ + b)*NSPLIT + sp)*C_ + c;
        s += g_psum[idx]; ss += g_psq[idx];
    }
    float mean = s * (1.f/N_);
    float var  = fmaxf(ss * (1.f/N_) - mean*mean, 0.f);
    g_mean[(t*B_ + b)*C_ + c] = mean;
    g_rstd[(t*B_ + b)*C_ + c] = rsqrtf(var + 1e-5f);
}

// ---------------- W transpose + fp16 convert ----------------
__global__ void k_wcvt(const float* __restrict__ Wq, const float* __restrict__ Wk,
                       const float* __restrict__ Wv){
    __shared__ float t[32][33];
    const float* W = (blockIdx.z == 0) ? Wq : (blockIdx.z == 1) ? Wk : Wv;
    __half* O = g_Wth + (size_t)blockIdx.z*C_*C_;
    const int k0 = blockIdx.x << 5, n0 = blockIdx.y << 5;
    for (int i = threadIdx.y; i < 32; i += 8)
        t[i][threadIdx.x] = W[(size_t)(k0 + i)*C_ + n0 + threadIdx.x];
    __syncthreads();
    for (int i = threadIdx.y; i < 32; i += 8)
        O[(size_t)(n0 + i)*C_ + k0 + threadIdx.x] = __float2half_rn(t[threadIdx.x][i]);
}

// ---------------- fused norm + 1x1 conv (fp16 HMMA) + epilogues ---------------
// grid (M_/64, 3): which = 0 Q (l2norm*log2e), 1 K (l2norm), 2 V (transpose)
__global__ __launch_bounds__(256) void k_qkv(const float* __restrict__ content,
                                             const float* __restrict__ style,
                                             const float* __restrict__ bq,
                                             const float* __restrict__ bk,
                                             const float* __restrict__ bv){
    __shared__ __align__(16) char smem[40960];   // AS[0:8192) WS[8192:40960); T/ssm overlay
    const uint32_t sb = s2u(smem);
    const int tid = threadIdx.x, warp = tid >> 5, lane = tid & 31;
    const int wq2 = warp >> 2, wc4 = warp & 3;
    const int mi = lane >> 3, r8 = lane & 7, l4 = lane >> 2, l2 = lane & 3;
    const int which = blockIdx.y;
    const int tm = blockIdx.x << 6;
    const int b = tm >> 12;
    const float* A = (which == 0) ? content : style;
    const float* bias = (which == 0) ? bq : (which == 1) ? bk : bv;
    const __half* wsrc = g_Wth + (size_t)which*C_*C_;
    const float* meanp = g_mean + (which == 1 ? B_*C_ : 0) + b*C_;
    const float* rstdp = g_rstd + (which == 1 ? B_*C_ : 0) + b*C_;
    const bool donorm = which < 2;

    float acc[2][8][4];
    #pragma unroll
    for (int mt = 0; mt < 2; mt++)
        #pragma unroll
        for (int ct = 0; ct < 8; ct++){
            acc[mt][ct][0] = 0.f; acc[mt][ct][1] = 0.f;
            acc[mt][ct][2] = 0.f; acc[mt][ct][3] = 0.f;
        }

    for (int kc = 0; kc < 4; kc++){
        __syncthreads();
        for (int it = tid; it < 2048; it += 256){
            int n = it >> 3, c16 = it & 7;
            cpa16(sb + 8192 + n*128 + (((uint32_t)(c16 ^ (n & 7))) << 4),
                  wsrc + (size_t)n*C_ + (kc << 6) + (c16 << 3));
        }
        CPCOMMIT();
        for (int it = tid; it < 1024; it += 256){
            int r = it >> 4, c4 = it & 15;
            int cc = (kc << 6) + (c4 << 2);
            float4 v = *(const float4*)(A + (size_t)(tm + r)*C_ + cc);
            if (donorm){
                float4 mn = *(const float4*)(meanp + cc);
                float4 rs = *(const float4*)(rstdp + cc);
                v.x = (v.x - mn.x)*rs.x; v.y = (v.y - mn.y)*rs.y;
                v.z = (v.z - mn.z)*rs.z; v.w = (v.w - mn.w)*rs.w;
            }
            __half2 h0 = __floats2half2_rn(v.x, v.y);
            __half2 h1 = __floats2half2_rn(v.z, v.w);
            uint2 u; u.x = *(uint32_t*)&h0; u.y = *(uint32_t*)&h1;
            int c16 = c4 >> 1, sub = c4 & 1;
            *(uint2*)(smem + (r << 7) + ((c16 ^ (r & 7)) << 4) + (sub << 3)) = u;
        }
        CPWAIT(0);
        __syncthreads();
        #pragma unroll
        for (int cs = 0; cs < 4; cs++){
            uint32_t colA = ((uint32_t)((2*cs + (mi >> 1)) ^ r8)) << 4;
            uint32_t a00,a01,a02,a03, a10,a11,a12,a13;
            uint32_t aAb = sb + (uint32_t)((wq2 << 5) + r8 + ((mi & 1) << 3))*128;
            ldm4(aAb + colA, a00,a01,a02,a03);
            ldm4(aAb + 16*128 + colA, a10,a11,a12,a13);
            uint32_t colB = ((uint32_t)((2*cs + (mi & 1)) ^ r8)) << 4;
            #pragma unroll
            for (int ctp = 0; ctp < 4; ctp++){
                uint32_t w0,w1,w2,w3;
                ldm4(sb + 8192 + (uint32_t)((wc4 << 6) + (ctp << 4) + r8 + ((mi >> 1) << 3))*128 + colB,
                     w0,w1,w2,w3);
                mma16816(acc[0][2*ctp],   a00,a01,a02,a03, w0,w1);
                mma16816(acc[0][2*ctp+1], a00,a01,a02,a03, w2,w3);
                mma16816(acc[1][2*ctp],   a10,a11,a12,a13, w0,w1);
                mma16816(acc[1][2*ctp+1], a10,a11,a12,a13, w2,w3);
            }
        }
    }
    __syncthreads();

    float ssq[2][2] = {{0.f,0.f},{0.f,0.f}};
    #pragma unroll
    for (int mt = 0; mt < 2; mt++)
        #pragma unroll
        for (int ct = 0; ct < 8; ct++){
            int ch = (wc4 << 6) + (ct << 3) + (l2 << 1);
            float2 bb = *(const float2*)(bias + ch);
            acc[mt][ct][0] += bb.x; acc[mt][ct][1] += bb.y;
            acc[mt][ct][2] += bb.x; acc[mt][ct][3] += bb.y;
            if (which < 2){
                ssq[mt][0] += acc[mt][ct][0]*acc[mt][ct][0] + acc[mt][ct][1]*acc[mt][ct][1];
                ssq[mt][1] += acc[mt][ct][2]*acc[mt][ct][2] + acc[mt][ct][3]*acc[mt][ct][3];
            }
        }

    if (which < 2){
        #pragma unroll
        for (int mt = 0; mt < 2; mt++)
            #pragma unroll
            for (int h = 0; h < 2; h++){
                float v = ssq[mt][h];
                v += __shfl_xor_sync(0xffffffffu, v, 1);
                v += __shfl_xor_sync(0xffffffffu, v, 2);
                ssq[mt][h] = v;
            }
        float* ssm = (float*)smem;    // [4][64]
        if (l2 == 0){
            #pragma unroll
            for (int mt = 0; mt < 2; mt++){
                int rl = (wq2 << 5) + (mt << 4) + l4;
                ssm[wc4*64 + rl]     = ssq[mt][0];
                ssm[wc4*64 + rl + 8] = ssq[mt][1];
            }
        }
        __syncthreads();
        const float qsc = (which == 0) ? L2E : 1.f;
        __half* O = (which == 0) ? g_Qh : g_Kh;
        #pragma unroll
        for (int mt = 0; mt < 2; mt++){
            int rl = (wq2 << 5) + (mt << 4) + l4;
            float scl = rsqrtf(ssm[rl] + ssm[64+rl] + ssm[128+rl] + ssm[192+rl] + 1e-12f) * qsc;
            int rh = rl + 8;
            float sch = rsqrtf(ssm[rh] + ssm[64+rh] + ssm[128+rh] + ssm[192+rh] + 1e-12f) * qsc;
            #pragma unroll
            for (int ct = 0; ct < 8; ct++){
                int ch = (wc4 << 6) + (ct << 3) + (l2 << 1);
                __half2 h = __floats2half2_rn(acc[mt][ct][0]*scl, acc[mt][ct][1]*scl);
                *(uint32_t*)(O + (size_t)(tm + rl)*C_ + ch) = *(uint32_t*)&h;
                h = __floats2half2_rn(acc[mt][ct][2]*sch, acc[mt][ct][3]*sch);
                *(uint32_t*)(O + (size_t)(tm + rh)*C_ + ch) = *(uint32_t*)&h;
            }
        }
    } else {
        __half* T = (__half*)smem;
        #pragma unroll
        for (int mt = 0; mt < 2; mt++){
            int rl = (wq2 << 5) + (mt << 4) + l4, rh = rl + 8;
            #pragma unroll
            for (int ct = 0; ct < 8; ct++){
                int ch = (wc4 << 6) + (ct << 3) + (l2 << 1);
                __half2 h = __floats2half2_rn(acc[mt][ct][0], acc[mt][ct][1]);
                *(uint32_t*)&T[rl*264 + ch] = *(uint32_t*)&h;
                h = __floats2half2_rn(acc[mt][ct][2], acc[mt][ct][3]);
                *(uint32_t*)&T[rh*264 + ch] = *(uint32_t*)&h;
            }
        }
        __syncthreads();
        const int c = tid;
        const int n0 = tm & (N_ - 1);
        __half* Ov = g_VTh + ((size_t)(b*C_ + c))*N_ + n0;
        #pragma unroll
        for (int j = 0; j < 8; j++){
            __half hh[8];
            #pragma unroll
            for (int i = 0; i < 8; i++) hh[i] = T[(j*8 + i)*264 + c];
            *(uint4*)(Ov + j*8) = *(uint4*)hh;
        }
    }
}

// ---------------- HMMA fused attention + AdaIN ----------------
// CTA = 64 queries x 256 channels x all 4096 keys. 256 threads (8 warps).
__global__ __launch_bounds__(256, 1) void k_attn_mma(const float* __restrict__ content,
                                                     float* __restrict__ out){
    extern __shared__ char sm[];
    const uint32_t sb = s2u(sm);
    const int tid = threadIdx.x, warp = tid >> 5, lane = tid & 31;
    const int q0 = blockIdx.x << 6;
    const int b  = q0 >> 12;
    const int wq = warp & 3, wk2 = warp >> 2;        // phase A tiling
    const int wq2 = warp >> 2, wc4 = warp & 3;       // phase B tiling
    const int mi = lane >> 3, r8 = lane & 7;
    const int l4 = lane >> 2, l2 = lane & 3;

    // prologue: Q + K(0), one cp.async group
    for (int it = tid; it < 2048; it += 256){
        int r = it >> 5, c16 = it & 31;
        cpa16(sb + QS_OFF + r*512 + (((uint32_t)(c16 ^ (r & 7))) << 4),
              g_Qh + (((size_t)(q0 + r)) << 8) + (c16 << 3));
    }
    for (int it = tid; it < 2048; it += 256){
        int r = it >> 5, c16 = it & 31;
        cpa16(sb + KS_OFF + r*512 + (((uint32_t)(c16 ^ (r & 7))) << 4),
              g_Kh + (((size_t)((b << 12) + r)) << 8) + (c16 << 3));
    }
    CPCOMMIT();
    CPWAIT(0);
    __syncthreads();

    // hoist Q fragments: 16 k-steps x 4 regs, live across all key tiles
    uint32_t qf[16][4];
    {
        const uint32_t aA = sb + QS_OFF + (uint32_t)((wq << 4) + r8 + ((mi & 1) << 3))*512;
        #pragma unroll
        for (int cs = 0; cs < 16; cs++)
            ldm4(aA + (((uint32_t)((2*cs + (mi >> 1)) ^ r8)) << 4),
                 qf[cs][0], qf[cs][1], qf[cs][2], qf[cs][3]);
    }

    float accM[2][8][4], accV2[2][8][4];
    #pragma unroll
    for (int mt = 0; mt < 2; mt++)
        #pragma unroll
        for (int ct = 0; ct < 8; ct++)
            #pragma unroll
            for (int j = 0; j < 4; j++){ accM[mt][ct][j] = 0.f; accV2[mt][ct][j] = 0.f; }
    float z0 = 0.f, z1 = 0.f;    // Z partials for rows (wq<<4)+l4 and +8

    const __half* vt_base = g_VTh + (size_t)b*C_*N_;

    for (int kt = 0; kt < 64; kt++){
        __syncthreads();     // previous tile's P/VT consumed
        // VT(kt): [256c][64k]
        for (int it = tid; it < 2048; it += 256){
            int r = it >> 3, c16 = it & 7;
            cpa16(sb + VTS_OFF + r*128 + (((uint32_t)(c16 ^ (r & 7))) << 4),
                  vt_base + (((size_t)r) << 12) + (kt << 6) + (c16 << 3));
        }
        CPCOMMIT();
        // K(kt+1) prefetch
        {
            int ktn = (kt + 1) & 63;
            uint32_t kdst = sb + KS_OFF + ((kt + 1) & 1)*32768;
            for (int it = tid; it < 2048; it += 256){
                int r = it >> 5, c16 = it & 31;
                cpa16(kdst + r*512 + (((uint32_t)(c16 ^ (r & 7))) << 4),
                      g_Kh + (((size_t)((b << 12) + (ktn << 6) + r)) << 8) + (c16 << 3));
            }
        }
        CPCOMMIT();
        CPWAIT(2);           // K(kt) ready
        __syncthreads();

        // ---- phase A: S = Q @ K^T, warp: 16q x 32k (Q frags in regs) ----
        const uint32_t kbase = sb + KS_OFF + (kt & 1)*32768;
        float d[4][4];
        #pragma unroll
        for (int i = 0; i < 4; i++){ d[i][0]=0.f; d[i][1]=0.f; d[i][2]=0.f; d[i][3]=0.f; }
        const uint32_t aB0 = kbase + (uint32_t)((wk2 << 5) + r8 + ((mi >> 1) << 3))*512;
        #pragma unroll
        for (int cs = 0; cs < 16; cs++){
            uint32_t b0,b1,b2,b3;
            uint32_t cB = ((uint32_t)((2*cs + (mi & 1)) ^ r8)) << 4;
            ldm4(aB0 + cB, b0,b1,b2,b3);
            mma16816(d[0], qf[cs][0], qf[cs][1], qf[cs][2], qf[cs][3], b0,b1);
            mma16816(d[1], qf[cs][0], qf[cs][1], qf[cs][2], qf[cs][3], b2,b3);
            ldm4(aB0 + 16*512 + cB, b0,b1,b2,b3);
            mma16816(d[2], qf[cs][0], qf[cs][1], qf[cs][2], qf[cs][3], b0,b1);
            mma16816(d[3], qf[cs][0], qf[cs][1], qf[cs][2], qf[cs][3], b2,b3);
        }
        // exp2 via MUFU f16x2; accumulate Z from the exact fp16 P values
        {
            const int qlo = (wq << 4) + l4;
            #pragma unroll
            for (int nt = 0; nt < 4; nt++){
                uint32_t plo = exp2_f16x2(d[nt][0], d[nt][1]);
                uint32_t phi = exp2_f16x2(d[nt][2], d[nt][3]);
                z0 += hsum2(plo);
                z1 += hsum2(phi);
                int c16p = (wk2 << 2) + nt;
                uint32_t sw = ((uint32_t)(c16p ^ l4)) << 4;
                *(uint32_t*)(sm + PS_OFF + qlo*128 + sw + (l2 << 2))       = plo;
                *(uint32_t*)(sm + PS_OFF + (qlo + 8)*128 + sw + (l2 << 2)) = phi;
            }
        }
        CPWAIT(1);           // VT(kt) ready
        __syncthreads();

        // ---- phase B: warp = 32q x 64ch; V^2 in regs ----
        const uint32_t aPb = sb + PS_OFF + (uint32_t)((wq2 << 5) + r8 + ((mi & 1) << 3))*128;
        const uint32_t aVb = sb + VTS_OFF + (uint32_t)((wc4 << 6) + r8 + ((mi >> 1) << 3))*128;
        #pragma unroll
        for (int s = 0; s < 4; s++){
            uint32_t colA = ((uint32_t)((2*s + (mi >> 1)) ^ r8)) << 4;
            uint32_t p00,p01,p02,p03, p10,p11,p12,p13;
            ldm4(aPb + colA, p00,p01,p02,p03);
            ldm4(aPb + 16*128 + colA, p10,p11,p12,p13);
            uint32_t colB = ((uint32_t)((2*s + (mi & 1)) ^ r8)) << 4;
            #pragma unroll
            for (int ctp = 0; ctp < 4; ctp++){
                uint32_t v0,v1,v2,v3;
                ldm4(aVb + (uint32_t)(ctp << 4)*128 + colB, v0,v1,v2,v3);
                mma16816(accM[0][2*ctp],   p00,p01,p02,p03, v0,v1);
                mma16816(accM[0][2*ctp+1], p00,p01,p02,p03, v2,v3);
                mma16816(accM[1][2*ctp],   p10,p11,p12,p13, v0,v1);
                mma16816(accM[1][2*ctp+1], p10,p11,p12,p13, v2,v3);
                uint32_t w0 = sqr2(v0), w1 = sqr2(v1), w2 = sqr2(v2), w3 = sqr2(v3);
                mma16816(accV2[0][2*ctp],   p00,p01,p02,p03, w0,w1);
                mma16816(accV2[0][2*ctp+1], p00,p01,p02,p03, w2,w3);
                mma16816(accV2[1][2*ctp],   p10,p11,p12,p13, w0,w1);
                mma16816(accV2[1][2*ctp+1], p10,p11,p12,p13, w2,w3);
            }
        }
    }
    CPWAIT(0);

    // ---- Z exchange: reduce over l2 lanes, then across wk2 via smem ----
    z0 += __shfl_xor_sync(0xffffffffu, z0, 1);
    z0 += __shfl_xor_sync(0xffffffffu, z0, 2);
    z1 += __shfl_xor_sync(0xffffffffu, z1, 1);
    z1 += __shfl_xor_sync(0xffffffffu, z1, 2);
    __syncthreads();                        // last phase B reads of P done
    float* Zs = (float*)(sm + PS_OFF);      // [64][2]
    if (l2 == 0){
        Zs[(((wq << 4) + l4) << 1) + wk2]     = z0;
        Zs[(((wq << 4) + l4 + 8) << 1) + wk2] = z1;
    }
    __syncthreads();

    // ---- epilogue: M/S2, AdaIN, store ----
    const float* meanp = g_mean + b*C_;
    const float* rstdp = g_rstd + b*C_;
    #pragma unroll
    for (int mt = 0; mt < 2; mt++){
        const int rloc = (wq2 << 5) + (mt << 4) + l4;
        const float izlo = 1.f / (Zs[rloc << 1] + Zs[(rloc << 1) + 1]);
        const float izhi = 1.f / (Zs[(rloc + 8) << 1] + Zs[((rloc + 8) << 1) + 1]);
        const int rl = q0 + rloc;
        const size_t glo = ((size_t)rl) << 8;
        const size_t ghi = ((size_t)(rl + 8)) << 8;
        #pragma unroll
        for (int ct = 0; ct < 8; ct++){
            const int ch = (wc4 << 6) + (ct << 3) + (l2 << 1);
            const float mn0 = meanp[ch], mn1 = meanp[ch+1];
            const float rs0 = rstdp[ch], rs1 = rstdp[ch+1];
            {
                float2 cv = *(const float2*)(content + glo + ch);
                float m = accM[mt][ct][0]*izlo;
                float s2 = accV2[mt][ct][0]*izlo - m*m;
                float s = s2 > 0.f ? sqrtf(s2) : 0.f;
                float2 o;
                o.x = s*((cv.x - mn0)*rs0) + m;
                m = accM[mt][ct][1]*izlo;
                s2 = accV2[mt][ct][1]*izlo - m*m;
                s = s2 > 0.f ? sqrtf(s2) : 0.f;
                o.y = s*((cv.y - mn1)*rs1) + m;
                *(float2*)(out + glo + ch) = o;
            }
            {
                float2 cv = *(const float2*)(content + ghi + ch);
                float m = accM[mt][ct][2]*izhi;
                float s2 = accV2[mt][ct][2]*izhi - m*m;
                float s = s2 > 0.f ? sqrtf(s2) : 0.f;
                float2 o;
                o.x = s*((cv.x - mn0)*rs0) + m;
                m = accM[mt][ct][3]*izhi;
                s2 = accV2[mt][ct][3]*izhi - m*m;
                s = s2 > 0.f ? sqrtf(s2) : 0.f;
                o.y = s*((cv.y - mn1)*rs1) + m;
                *(float2*)(out + ghi + ch) = o;
            }
        }
    }
}

// ---------------- launch ----------------
extern "C" void kernel_launch(void* const* d_in, const int* in_sizes, int n_in,
                              void* d_out, int out_size){
    const float* content = (const float*)d_in[0];
    const float* style   = (const float*)d_in[1];
    const float* Wq = (const float*)d_in[2];
    const float* bq = (const float*)d_in[3];
    const float* Wk = (const float*)d_in[4];
    const float* bk = (const float*)d_in[5];
    const float* Wv = (const float*)d_in[6];
    const float* bv = (const float*)d_in[7];
    float* out = (float*)d_out;

    cudaFuncSetAttribute(k_attn_mma, cudaFuncAttributeMaxDynamicSharedMemorySize, SMEM_ATT);

    k_stats_partial<<<dim3(NSPLIT, B_, 2), 256>>>(content, style);
    k_stats_final<<<dim3(B_, 2), 256>>>();
    k_wcvt<<<dim3(8, 8, 3), dim3(32, 8)>>>(Wq, Wk, Wv);
    k_qkv<<<dim3(M_/64, 3), 256>>>(content, style, bq, bk, bv);
    k_attn_mma<<<M_/64, 256, SMEM_ATT>>>(content, out);
}